// round 11
// baseline (speedup 1.0000x reference)
#include <cuda_runtime.h>
#include <cuda_fp16.h>
#include <math.h>
#include <stdint.h>

#define NB 131072
#define NH 512
#define NL 256
#define NKC 1024
#define NF 267
#define CAP 65536
#define KTILE 32
#define TILE_F (KTILE * 256)
#define SMEM_BYTES (2 * 2 * TILE_F * 4)

typedef unsigned long long u64;
typedef unsigned int u32;

// ---------------- scratch ----------------
__device__ float  g_enorm[NKC];
__device__ u64    g_key[NB];
__device__ u64    g_tb[(size_t)NB * 8];
__device__ u64    g_ts[(size_t)NB * 8];
__device__ int    g_counts[NKC];
__device__ double g_loss;
__device__ int    g_rcount;
__device__ int    g_flag[CAP];
__device__ u64    g_rkeys[CAP];
// repair fp32 buffers
__device__ float  g_rx[(size_t)CAP * NF];
__device__ float  g_rc[(size_t)CAP * NF];
__device__ float  g_rh1[(size_t)CAP * NH];
__device__ float  g_rh2[(size_t)CAP * NH];
__device__ float  g_rmu[(size_t)CAP * NL];
// fp16 activation planes
__device__ __half g_PXh[(size_t)NB * 544], g_PXl[(size_t)NB * 544];
__device__ __half g_PAh[(size_t)NB * 544], g_PAl[(size_t)NB * 544];
__device__ __half g_PBh[(size_t)NB * 512], g_PBl[(size_t)NB * 512];
__device__ __half g_PCh[(size_t)NB * 512], g_PCl[(size_t)NB * 512];
__device__ __half g_PMh[(size_t)NB * 256], g_PMl[(size_t)NB * 256];
// fp16 weight planes [Npad][Kpad]
__device__ __half g_w1h[512 * 544], g_w1l[512 * 544];
__device__ __half g_w2h[512 * 512], g_w2l[512 * 512];
__device__ __half g_w3h[512 * 512], g_w3l[512 * 512];
__device__ __half g_wmh[256 * 512], g_wml[256 * 512];
__device__ __half g_w4h[512 * 544], g_w4l[512 * 544];
__device__ __half g_w5h[512 * 512], g_w5l[512 * 512];
__device__ __half g_w6h[512 * 512], g_w6l[512 * 512];
__device__ __half g_woh[384 * 512], g_wol[384 * 512];
__device__ __half g_ebh[1024 * 256], g_ebl[1024 * 256];

#define FFMA2(d, a, b) asm("fma.rn.f32x2 %0, %1, %2, %0;" : "+l"(d) : "l"(a), "l"(b))
__device__ __forceinline__ u64 dupf(float v) {
    u64 r; asm("mov.b64 %0, {%1, %1};" : "=l"(r) : "f"(v)); return r;
}
__device__ __forceinline__ float lof(u64 v) { return __uint_as_float((unsigned)v); }
__device__ __forceinline__ float hif(u64 v) { return __uint_as_float((unsigned)(v >> 32)); }
__device__ __forceinline__ u32 smem_u32(const void* p) {
    u32 a;
    asm("{ .reg .u64 t; cvta.to.shared.u64 t, %1; cvt.u32.u64 %0, t; }" : "=r"(a) : "l"(p));
    return a;
}
__device__ __forceinline__ void ldsm4(u32* r, u32 addr) {
    asm volatile("ldmatrix.sync.aligned.m8n8.x4.shared.b16 {%0,%1,%2,%3}, [%4];"
        : "=r"(r[0]), "=r"(r[1]), "=r"(r[2]), "=r"(r[3]) : "r"(addr));
}
__device__ __forceinline__ void mmah(float* c, const u32* a, u32 b0, u32 b1) {
    asm volatile("mma.sync.aligned.m16n8k16.row.col.f32.f16.f16.f32 "
        "{%0,%1,%2,%3}, {%4,%5,%6,%7}, {%8,%9}, {%0,%1,%2,%3};"
        : "+f"(c[0]), "+f"(c[1]), "+f"(c[2]), "+f"(c[3])
        : "r"(a[0]), "r"(a[1]), "r"(a[2]), "r"(a[3]), "r"(b0), "r"(b1));
}
__device__ __forceinline__ u64 enc_key(float d, int col) {
    unsigned u = __float_as_uint(d);
    u = (u & 0x80000000u) ? ~u : (u | 0x80000000u);
    return ((u64)u << 32) | (unsigned)col;
}
__device__ __forceinline__ float dec_key(u64 k) {
    unsigned u = (unsigned)(k >> 32);
    u = (u & 0x80000000u) ? (u & 0x7FFFFFFFu) : ~u;
    return __uint_as_float(u);
}
__device__ __forceinline__ void mergeBS(u64& b, u64& s, u64 b2, u64 s2) {
    if (b2 < b) { u64 t = b < s2 ? b : s2; b = b2; s = t; }
    else        { if (b2 < s) s = b2; }
}

// ======================= fp32 FFMA2 GEMM (repair path) =====================
template <int MODE>   // 0 relu, 1 linear, 2 VQ argmin
__global__ void __launch_bounds__(256, 1) gemm2(
    const float* __restrict__ A0, int K0,
    const float* __restrict__ A1, int Ktot,
    const float* __restrict__ W, const float* __restrict__ bias,
    float* __restrict__ C, int N, u64* __restrict__ keys,
    const int* __restrict__ cnt)
{
    extern __shared__ float dyn[];
    float* As = dyn;
    float* Ws = dyn + 2 * TILE_F;

    const int tid = threadIdx.x;
    const int tx = tid & 15, ty = tid >> 4;
    const int m0 = blockIdx.x * 128, n0 = blockIdx.y * 256;
    if (cnt) { int n = *cnt; if (n > CAP) n = CAP; if (m0 >= n) return; }
    const int K1 = Ktot - K0;
    const int am = tid >> 1;
    const int ak = (tid & 1) * 16;
    const int nT = (Ktot + KTILE - 1) / KTILE;

    u64 acc[8][8];
#pragma unroll
    for (int i = 0; i < 8; ++i)
#pragma unroll
        for (int j = 0; j < 8; ++j) acc[i][j] = 0ull;

    float  aReg[16];
    float4 bReg[8];

#define LOADA(kt) do {                                                        \
    _Pragma("unroll")                                                         \
    for (int q = 0; q < 16; ++q) {                                            \
        int k = (kt) * KTILE + ak + q;                                        \
        float v = 0.f;                                                        \
        if (k < K0)        v = A0[(size_t)(m0 + am) * K0 + k];                \
        else if (k < Ktot) v = A1[(size_t)(m0 + am) * K1 + (k - K0)];         \
        aReg[q] = v;                                                          \
    } } while (0)

#define LOADB(kt) do {                                                        \
    _Pragma("unroll")                                                         \
    for (int i = 0; i < 8; ++i) {                                             \
        int idx = tid + i * 256;                                              \
        int k = idx >> 6, n4 = (idx & 63) * 4;                                \
        int kg = (kt) * KTILE + k;                                            \
        int ng = n0 + n4;                                                     \
        float4 v = make_float4(0.f, 0.f, 0.f, 0.f);                           \
        if (kg < Ktot && ng < N) v = *(const float4*)&W[(size_t)kg * N + ng]; \
        bReg[i] = v;                                                          \
    } } while (0)

#define STST(p) do {                                                          \
    float* ab = As + (p) * TILE_F;                                            \
    _Pragma("unroll")                                                         \
    for (int q = 0; q < 16; ++q)                                              \
        *(u64*)(ab + (ak + q) * 256 + 2 * am) = dupf(aReg[q]);                \
    float* wb = Ws + (p) * TILE_F;                                            \
    _Pragma("unroll")                                                         \
    for (int i = 0; i < 8; ++i) {                                             \
        int idx = tid + i * 256;                                              \
        *(float4*)(wb + (idx >> 6) * 256 + (idx & 63) * 4) = bReg[i];         \
    } } while (0)

    LOADA(0); LOADB(0);
    STST(0);
    __syncthreads();

    for (int kt = 0; kt < nT; ++kt) {
        const int p = kt & 1;
        if (kt + 1 < nT) { LOADA(kt + 1); LOADB(kt + 1); }
        const float* ab = As + p * TILE_F + ty * 16;
        const float* wb = Ws + p * TILE_F + tx * 4;
#pragma unroll 4
        for (int k = 0; k < KTILE; ++k) {
            u64 a[8], b[8];
            const ulonglong2* ap = (const ulonglong2*)(ab + k * 256);
#pragma unroll
            for (int q = 0; q < 4; ++q) { ulonglong2 t = ap[q]; a[2*q] = t.x; a[2*q+1] = t.y; }
#pragma unroll
            for (int q = 0; q < 4; ++q) {
                ulonglong2 t = *(const ulonglong2*)(wb + k * 256 + q * 64);
                b[2*q] = t.x; b[2*q+1] = t.y;
            }
#pragma unroll
            for (int i = 0; i < 8; ++i)
#pragma unroll
                for (int j = 0; j < 8; ++j) FFMA2(acc[i][j], a[i], b[j]);
        }
        if (kt + 1 < nT) STST((kt + 1) & 1);
        __syncthreads();
    }

    if (MODE == 2) {
        u64* red = (u64*)dyn;
#pragma unroll
        for (int i = 0; i < 8; ++i) {
            u64 best = ~0ull;
#pragma unroll
            for (int j = 0; j < 8; ++j) {
                int c0 = n0 + (j >> 1) * 64 + tx * 4 + (j & 1) * 2;
                u64 k0 = enc_key(bias[c0]     - 2.f * lof(acc[i][j]), c0);
                u64 k1 = enc_key(bias[c0 + 1] - 2.f * hif(acc[i][j]), c0 + 1);
                if (k0 < best) best = k0;
                if (k1 < best) best = k1;
            }
            red[(ty * 8 + i) * 17 + tx] = best;
        }
        __syncthreads();
        if (tid < 128) {
            u64 b = red[tid * 17];
#pragma unroll
            for (int x = 1; x < 16; ++x) { u64 v = red[tid * 17 + x]; if (v < b) b = v; }
            atomicMin(&keys[m0 + tid], b);
        }
        return;
    }

#pragma unroll
    for (int i = 0; i < 8; ++i) {
        size_t row = (size_t)(m0 + ty * 8 + i);
#pragma unroll
        for (int j = 0; j < 8; ++j) {
            int c0 = n0 + (j >> 1) * 64 + tx * 4 + (j & 1) * 2;
            if (c0 < N) {
                float v = lof(acc[i][j]) + bias[c0];
                if (MODE == 0) v = fmaxf(v, 0.f);
                C[row * N + c0] = v;
            }
            if (c0 + 1 < N) {
                float v = hif(acc[i][j]) + bias[c0 + 1];
                if (MODE == 0) v = fmaxf(v, 0.f);
                C[row * N + c0 + 1] = v;
            }
        }
    }
#undef LOADA
#undef LOADB
#undef STST
}

// ======= fp16-plane mma.sync GEMM, cp.async 3-stage (R8 config) ============
// MODE 0: relu -> planes (3-term) | 1: linear -> fp32, N guard (3-term)
// MODE 2: VQ best/second (1-term: margin+repair absorbs the fp16 noise)
// MODE 4: linear -> planes only (3-term)
#define FSTG 32768
#define SMEM_F (3 * FSTG)

template <int MODE>
__global__ void __launch_bounds__(256, 1) fgemm(
    const __half* __restrict__ Ah, const __half* __restrict__ Al, int lda,
    const __half* __restrict__ Bh, const __half* __restrict__ Bl, int ldb,
    const float* __restrict__ bias, int Ktot,
    float* __restrict__ outF, __half* __restrict__ outH, __half* __restrict__ outL,
    int ldo, int N, u64* __restrict__ tb, u64* __restrict__ ts)
{
    extern __shared__ char smraw[];
    const u32 smem = smem_u32(smraw);

    const int tid = threadIdx.x;
    const int lane = tid & 31, wid = tid >> 5;
    const int wm = (wid >> 1) * 32, wn = (wid & 1) * 64;
    const int g = lane >> 2, tg = lane & 3;
    const int m0 = blockIdx.x * 128, n0 = blockIdx.y * 128;
    const int nT = Ktot >> 5;

    const int lx = lane & 7;
    const int mA = wm + lx + ((lane & 8) ? 8 : 0);
    const int cA = (lane >> 4) & 1;
    const int nB = wn + lx + ((lane & 16) ? 8 : 0);
    const int cB = (lane >> 3) & 1;

    float acc[2][8][4];
#pragma unroll
    for (int mt = 0; mt < 2; ++mt)
#pragma unroll
        for (int j = 0; j < 8; ++j)
#pragma unroll
            for (int q = 0; q < 4; ++q) acc[mt][j][q] = 0.f;

// For MODE==2 only hi chunks (cc<4) are loaded/used.
#define ISSUE(kt) do {                                                         \
    u32 st = smem + ((kt) % 3) * FSTG;                                         \
    _Pragma("unroll")                                                          \
    for (int i = 0; i < 4; ++i) {                                              \
        int idx = tid + i * 256; int m = idx >> 3, cc = idx & 7;               \
        if (MODE == 2 && cc >= 4) continue;                                    \
        const __half* src = (cc < 4 ? Ah : Al)                                 \
            + (size_t)(m0 + m) * lda + (kt) * 32 + (cc & 3) * 8;               \
        u32 dst = st + m * 128 + ((cc ^ (m & 7)) << 4);                        \
        asm volatile("cp.async.ca.shared.global [%0], [%1], 16;"               \
                     :: "r"(dst), "l"(src));                                   \
    }                                                                          \
    _Pragma("unroll")                                                          \
    for (int i = 0; i < 4; ++i) {                                              \
        int idx = tid + i * 256; int n = idx >> 3, cc = idx & 7;               \
        if (MODE == 2 && cc >= 4) continue;                                    \
        const __half* src = (cc < 4 ? Bh : Bl)                                 \
            + (size_t)(n0 + n) * ldb + (kt) * 32 + (cc & 3) * 8;               \
        u32 dst = st + 16384 + n * 128 + ((cc ^ (n & 7)) << 4);                \
        asm volatile("cp.async.ca.shared.global [%0], [%1], 16;"               \
                     :: "r"(dst), "l"(src));                                   \
    }                                                                          \
    asm volatile("cp.async.commit_group;"); } while (0)

    ISSUE(0); ISSUE(1);

    for (int kt = 0; kt < nT; ++kt) {
        if (kt + 1 < nT) asm volatile("cp.async.wait_group 1;");
        else             asm volatile("cp.async.wait_group 0;");
        __syncthreads();

        const u32 Abase = smem + (kt % 3) * FSTG;
        const u32 Bbase = Abase + 16384;
#pragma unroll
        for (int s = 0; s < 2; ++s) {
            u32 ah[2][4], al[2][4];
#pragma unroll
            for (int mt = 0; mt < 2; ++mt) {
                u32 rowa = Abase + (mA + mt * 16) * 128;
                int ch = 2 * s + cA;
                ldsm4(ah[mt], rowa + ((ch ^ lx) << 4));
                if (MODE != 2) ldsm4(al[mt], rowa + (((ch + 4) ^ lx) << 4));
            }
            u32 bh[4][4], bl[4][4];
#pragma unroll
            for (int jp = 0; jp < 4; ++jp) {
                u32 rowb = Bbase + (nB + jp * 16) * 128;
                int ch = 2 * s + cB;
                ldsm4(bh[jp], rowb + ((ch ^ lx) << 4));
                if (MODE != 2) ldsm4(bl[jp], rowb + (((ch + 4) ^ lx) << 4));
            }
#pragma unroll
            for (int mt = 0; mt < 2; ++mt)
#pragma unroll
                for (int jp = 0; jp < 4; ++jp)
#pragma unroll
                    for (int jj = 0; jj < 2; ++jj) {
                        float* a = acc[mt][jp * 2 + jj];
                        mmah(a, ah[mt], bh[jp][2*jj], bh[jp][2*jj+1]);
                        if (MODE != 2) {
                            mmah(a, ah[mt], bl[jp][2*jj], bl[jp][2*jj+1]);
                            mmah(a, al[mt], bh[jp][2*jj], bh[jp][2*jj+1]);
                        }
                    }
        }
        if (kt + 2 < nT) ISSUE(kt + 2);
    }
#undef ISSUE

    if (MODE == 2) {
        __syncthreads();
        u64* pb = (u64*)smraw;          // [128][8]
        u64* ps = pb + 128 * 8;
        const int slot = (wid & 1) * 4 + tg;
#pragma unroll
        for (int mt = 0; mt < 2; ++mt)
#pragma unroll
            for (int dq = 0; dq < 2; ++dq) {
                int rl = wm + mt * 16 + g + dq * 8;
                u64 b = ~0ull, s = ~0ull;
#pragma unroll
                for (int j = 0; j < 8; ++j)
#pragma unroll
                    for (int c01 = 0; c01 < 2; ++c01) {
                        int col = n0 + wn + j * 8 + 2 * tg + c01;
                        u64 k = enc_key(bias[col] - 2.f * acc[mt][j][dq * 2 + c01], col);
                        if (k < b) { s = b; b = k; } else if (k < s) s = k;
                    }
                pb[rl * 8 + slot] = b;
                ps[rl * 8 + slot] = s;
            }
        __syncthreads();
        if (tid < 128) {
            u64 b = pb[tid * 8], s = ps[tid * 8];
#pragma unroll
            for (int k = 1; k < 8; ++k) mergeBS(b, s, pb[tid * 8 + k], ps[tid * 8 + k]);
            tb[(size_t)(m0 + tid) * 8 + blockIdx.y] = b;
            ts[(size_t)(m0 + tid) * 8 + blockIdx.y] = s;
        }
        return;
    }

#pragma unroll
    for (int mt = 0; mt < 2; ++mt) {
        int r0 = m0 + wm + mt * 16 + g;
#pragma unroll
        for (int j = 0; j < 8; ++j) {
            int c0 = n0 + wn + j * 8 + 2 * tg;
            if (MODE == 0 || MODE == 4) {
                float b0 = bias[c0], b1 = bias[c0 + 1];
                float v0 = acc[mt][j][0] + b0, v1 = acc[mt][j][1] + b1;
                float v2 = acc[mt][j][2] + b0, v3 = acc[mt][j][3] + b1;
                if (MODE == 0) {
                    v0 = fmaxf(v0, 0.f); v1 = fmaxf(v1, 0.f);
                    v2 = fmaxf(v2, 0.f); v3 = fmaxf(v3, 0.f);
                }
                __half h0 = __float2half_rn(v0), h1 = __float2half_rn(v1);
                __half h2 = __float2half_rn(v2), h3 = __float2half_rn(v3);
                *(__half2*)(outH + (size_t)r0 * ldo + c0) = __halves2half2(h0, h1);
                *(__half2*)(outH + (size_t)(r0 + 8) * ldo + c0) = __halves2half2(h2, h3);
                *(__half2*)(outL + (size_t)r0 * ldo + c0) = __halves2half2(
                    __float2half_rn(v0 - __half2float(h0)),
                    __float2half_rn(v1 - __half2float(h1)));
                *(__half2*)(outL + (size_t)(r0 + 8) * ldo + c0) = __halves2half2(
                    __float2half_rn(v2 - __half2float(h2)),
                    __float2half_rn(v3 - __half2float(h3)));
            } else {
                float b0 = (c0 < N) ? bias[c0] : 0.f;
                float b1 = (c0 + 1 < N) ? bias[c0 + 1] : 0.f;
                if (c0 < N) {
                    outF[(size_t)r0 * ldo + c0]       = acc[mt][j][0] + b0;
                    outF[(size_t)(r0 + 8) * ldo + c0] = acc[mt][j][2] + b0;
                }
                if (c0 + 1 < N) {
                    outF[(size_t)r0 * ldo + c0 + 1]       = acc[mt][j][1] + b1;
                    outF[(size_t)(r0 + 8) * ldo + c0 + 1] = acc[mt][j][3] + b1;
                }
            }
        }
    }
}

// ======================= prep / combine / repair kernels ===================
__global__ void init_kernel() {
    int t = blockIdx.x * 256 + threadIdx.x;
    if (t < NKC) g_counts[t] = 0;
    if (t < CAP) g_rkeys[t] = ~0ull;
    if (t == 0) { g_loss = 0.0; g_rcount = 0; }
}
__global__ void enorm_kernel(const float* __restrict__ e) {
    int k = blockIdx.x * 256 + threadIdx.x;
    float s = 0.f;
    for (int l = 0; l < NL; ++l) { float v = e[(size_t)l * NKC + k]; s += v * v; }
    g_enorm[k] = s;
}
__global__ void wsplit_kernel(const float* __restrict__ W, int K, int N, int Kpad,
                              __half* __restrict__ H, __half* __restrict__ L) {
    int n = blockIdx.x;
    int k = blockIdx.y * 256 + threadIdx.x;
    if (k >= Kpad) return;
    float v = (k < K && n < N) ? W[(size_t)k * N + n] : 0.f;
    __half h = __float2half_rn(v);
    size_t o = (size_t)n * Kpad + k;
    H[o] = h;
    L[o] = __float2half_rn(v - __half2float(h));
}
__global__ void xcsplit_kernel(const float* __restrict__ x, const float* __restrict__ c,
                               __half* __restrict__ H, __half* __restrict__ L) {
    size_t r = blockIdx.x; int j = threadIdx.x;
    float v = 0.f;
    if (j < NF) v = x[r * NF + j];
    else if (j < 2 * NF) v = c[r * NF + j - NF];
    __half h = __float2half_rn(v);
    H[r * 544 + j] = h;
    L[r * 544 + j] = __float2half_rn(v - __half2float(h));
}
__global__ void csplit_kernel(const float* __restrict__ c,
                              __half* __restrict__ H, __half* __restrict__ L) {
    size_t r = blockIdx.x; int j = threadIdx.x;
    float v = (j < NF) ? c[r * NF + j] : 0.f;
    __half h = __float2half_rn(v);
    H[r * 544 + 256 + j] = h;
    L[r * 544 + 256 + j] = __float2half_rn(v - __half2float(h));
}
__global__ void combine_kernel() {
    int row = blockIdx.x * 256 + threadIdx.x;
    u64 b = g_tb[(size_t)row * 8], s = g_ts[(size_t)row * 8];
#pragma unroll
    for (int t = 1; t < 8; ++t) mergeBS(b, s, g_tb[(size_t)row * 8 + t], g_ts[(size_t)row * 8 + t]);
    g_key[row] = b;
    float d1 = dec_key(b), d2 = dec_key(s);
    if (d2 - d1 < 0.25f + 1e-3f * fabsf(d1)) {
        int pos = atomicAdd(&g_rcount, 1);
        if (pos < CAP) g_flag[pos] = row;
    }
}
__global__ void rgather_kernel(const float* __restrict__ x, const float* __restrict__ c) {
    int n = g_rcount; if (n > CAP) n = CAP;
    int i = blockIdx.x * 8 + (threadIdx.x >> 5);
    if (i >= n) return;
    int lane = threadIdx.x & 31;
    size_t row = (size_t)g_flag[i];
    for (int j = lane; j < NF; j += 32) {
        g_rx[(size_t)i * NF + j] = x[row * NF + j];
        g_rc[(size_t)i * NF + j] = c[row * NF + j];
    }
}
__global__ void rscatter_kernel() {
    int n = g_rcount; if (n > CAP) n = CAP;
    int i = blockIdx.x * 256 + threadIdx.x;
    if (i < n) g_key[g_flag[i]] = g_rkeys[i];
}
// counts, loss (from planes), decoder-input quantize planes (from embed planes)
__global__ void vq_gather_kernel(const __half* __restrict__ pmh, const __half* __restrict__ pml,
                                 const __half* __restrict__ ebh, const __half* __restrict__ ebl,
                                 __half* __restrict__ H, __half* __restrict__ L) {
    __shared__ float s_ls[8];
    const int wid = threadIdx.x >> 5, lane = threadIdx.x & 31;
    const size_t row = (size_t)blockIdx.x * 8 + wid;
    const int ind = (int)(g_key[row] & 0xFFFFFFFFull);
    if (lane == 0) atomicAdd(&g_counts[ind], 1);
    float ls = 0.f;
#pragma unroll
    for (int i = 0; i < 8; ++i) {
        int dim = i * 32 + lane;
        __half qh = ebh[(size_t)ind * 256 + dim];
        __half ql = ebl[(size_t)ind * 256 + dim];
        float qv = __half2float(qh) + __half2float(ql);
        float mv = __half2float(pmh[row * 256 + dim]) + __half2float(pml[row * 256 + dim]);
        H[row * 544 + dim] = qh;
        L[row * 544 + dim] = ql;
        float d = qv - mv;
        ls += d * d;
    }
#pragma unroll
    for (int s = 16; s > 0; s >>= 1) ls += __shfl_down_sync(0xFFFFFFFF, ls, s);
    if (lane == 0) s_ls[wid] = ls;
    __syncthreads();
    if (threadIdx.x == 0) {
        double t = 0.0;
        for (int w = 0; w < 8; ++w) t += (double)s_ls[w];
        atomicAdd(&g_loss, t);
    }
}
__global__ void finalize_kernel(float* __restrict__ out) {
    __shared__ double sh[256];
    int t = threadIdx.x;
    double e = 0.0;
    for (int k = t; k < NKC; k += 256) {
        double p = (double)g_counts[k] / (double)NB;
        e += p * log(p + 1e-10);
    }
    sh[t] = e;
    __syncthreads();
    for (int s = 128; s > 0; s >>= 1) { if (t < s) sh[t] += sh[t + s]; __syncthreads(); }
    if (t == 0) {
        out[(size_t)NB * NF]     = (float)(g_loss / ((double)NB * (double)NL));
        out[(size_t)NB * NF + 1] = (float)exp(-sh[0]);
    }
}

// ======================= launch ===========================================
extern "C" void kernel_launch(void* const* d_in, const int* in_sizes, int n_in,
                              void* d_out, int out_size)
{
    const float* x     = (const float*)d_in[0];
    const float* c     = (const float*)d_in[1];
    const float* W1    = (const float*)d_in[2];
    const float* b1    = (const float*)d_in[3];
    const float* W2    = (const float*)d_in[4];
    const float* b2    = (const float*)d_in[5];
    const float* W3    = (const float*)d_in[6];
    const float* b3    = (const float*)d_in[7];
    const float* Wmu   = (const float*)d_in[8];
    const float* bmu   = (const float*)d_in[9];
    const float* W4    = (const float*)d_in[10];
    const float* b4    = (const float*)d_in[11];
    const float* W5    = (const float*)d_in[12];
    const float* b5    = (const float*)d_in[13];
    const float* W6    = (const float*)d_in[14];
    const float* b6    = (const float*)d_in[15];
    const float* Wo    = (const float*)d_in[16];
    const float* bo    = (const float*)d_in[17];
    const float* embed = (const float*)d_in[18];
    float* out = (float*)d_out;

    float *en, *rx, *rc, *rh1, *rh2, *rmu;
    u64 *keys, *tb, *ts, *rkeys;
    int* rcnt;
    __half *pxh, *pxl, *pah, *pal, *pbh, *pbl, *pch, *pcl, *pmh, *pml;
    __half *w1h, *w1l, *w2h, *w2l, *w3h, *w3l, *wmh, *wml;
    __half *w4h, *w4l, *w5h, *w5l, *w6h, *w6l, *woh, *wol, *ebh, *ebl;
    cudaGetSymbolAddress((void**)&en,   g_enorm);
    cudaGetSymbolAddress((void**)&keys, g_key);
    cudaGetSymbolAddress((void**)&tb,   g_tb);
    cudaGetSymbolAddress((void**)&ts,   g_ts);
    cudaGetSymbolAddress((void**)&rkeys, g_rkeys);
    cudaGetSymbolAddress((void**)&rcnt, g_rcount);
    cudaGetSymbolAddress((void**)&rx,   g_rx);
    cudaGetSymbolAddress((void**)&rc,   g_rc);
    cudaGetSymbolAddress((void**)&rh1,  g_rh1);
    cudaGetSymbolAddress((void**)&rh2,  g_rh2);
    cudaGetSymbolAddress((void**)&rmu,  g_rmu);
    cudaGetSymbolAddress((void**)&pxh,  g_PXh);
    cudaGetSymbolAddress((void**)&pxl,  g_PXl);
    cudaGetSymbolAddress((void**)&pah,  g_PAh);
    cudaGetSymbolAddress((void**)&pal,  g_PAl);
    cudaGetSymbolAddress((void**)&pbh,  g_PBh);
    cudaGetSymbolAddress((void**)&pbl,  g_PBl);
    cudaGetSymbolAddress((void**)&pch,  g_PCh);
    cudaGetSymbolAddress((void**)&pcl,  g_PCl);
    cudaGetSymbolAddress((void**)&pmh,  g_PMh);
    cudaGetSymbolAddress((void**)&pml,  g_PMl);
    cudaGetSymbolAddress((void**)&w1h,  g_w1h);  cudaGetSymbolAddress((void**)&w1l, g_w1l);
    cudaGetSymbolAddress((void**)&w2h,  g_w2h);  cudaGetSymbolAddress((void**)&w2l, g_w2l);
    cudaGetSymbolAddress((void**)&w3h,  g_w3h);  cudaGetSymbolAddress((void**)&w3l, g_w3l);
    cudaGetSymbolAddress((void**)&wmh,  g_wmh);  cudaGetSymbolAddress((void**)&wml, g_wml);
    cudaGetSymbolAddress((void**)&w4h,  g_w4h);  cudaGetSymbolAddress((void**)&w4l, g_w4l);
    cudaGetSymbolAddress((void**)&w5h,  g_w5h);  cudaGetSymbolAddress((void**)&w5l, g_w5l);
    cudaGetSymbolAddress((void**)&w6h,  g_w6h);  cudaGetSymbolAddress((void**)&w6l, g_w6l);
    cudaGetSymbolAddress((void**)&woh,  g_woh);  cudaGetSymbolAddress((void**)&wol, g_wol);
    cudaGetSymbolAddress((void**)&ebh,  g_ebh);  cudaGetSymbolAddress((void**)&ebl, g_ebl);

    cudaFuncSetAttribute(gemm2<0>, cudaFuncAttributeMaxDynamicSharedMemorySize, SMEM_BYTES);
    cudaFuncSetAttribute(gemm2<1>, cudaFuncAttributeMaxDynamicSharedMemorySize, SMEM_BYTES);
    cudaFuncSetAttribute(gemm2<2>, cudaFuncAttributeMaxDynamicSharedMemorySize, SMEM_BYTES);
    cudaFuncSetAttribute(fgemm<0>, cudaFuncAttributeMaxDynamicSharedMemorySize, SMEM_F);
    cudaFuncSetAttribute(fgemm<1>, cudaFuncAttributeMaxDynamicSharedMemorySize, SMEM_F);
    cudaFuncSetAttribute(fgemm<2>, cudaFuncAttributeMaxDynamicSharedMemorySize, SMEM_F);
    cudaFuncSetAttribute(fgemm<4>, cudaFuncAttributeMaxDynamicSharedMemorySize, SMEM_F);

    const int MT = NB / 128;   // 1024
    const int RT = CAP / 128;  // 512
    init_kernel<<<256, 256>>>();
    enorm_kernel<<<4, 256>>>(embed);
    wsplit_kernel<<<dim3(512, 3), 256>>>(W1, 534, 512, 544, w1h, w1l);
    wsplit_kernel<<<dim3(512, 2), 256>>>(W2, 512, 512, 512, w2h, w2l);
    wsplit_kernel<<<dim3(512, 2), 256>>>(W3, 512, 512, 512, w3h, w3l);
    wsplit_kernel<<<dim3(256, 2), 256>>>(Wmu, 512, 256, 512, wmh, wml);
    wsplit_kernel<<<dim3(512, 3), 256>>>(W4, 523, 512, 544, w4h, w4l);
    wsplit_kernel<<<dim3(512, 2), 256>>>(W5, 512, 512, 512, w5h, w5l);
    wsplit_kernel<<<dim3(512, 2), 256>>>(W6, 512, 512, 512, w6h, w6l);
    wsplit_kernel<<<dim3(384, 2), 256>>>(Wo, 512, 267, 512, woh, wol);
    wsplit_kernel<<<dim3(1024, 1), 256>>>(embed, 256, 1024, 256, ebh, ebl);
    xcsplit_kernel<<<NB, 544>>>(x, c, pxh, pxl);
    csplit_kernel<<<NB, 288>>>(c, pah, pal);

    // encoder (fp16 planes, 3-term)
    fgemm<0><<<dim3(MT, 4), 256, SMEM_F>>>(pxh, pxl, 544, w1h, w1l, 544, b1, 544, 0, pbh, pbl, 512, 512, 0, 0);
    fgemm<0><<<dim3(MT, 4), 256, SMEM_F>>>(pbh, pbl, 512, w2h, w2l, 512, b2, 512, 0, pch, pcl, 512, 512, 0, 0);
    fgemm<0><<<dim3(MT, 4), 256, SMEM_F>>>(pch, pcl, 512, w3h, w3l, 512, b3, 512, 0, pbh, pbl, 512, 512, 0, 0);
    fgemm<4><<<dim3(MT, 2), 256, SMEM_F>>>(pbh, pbl, 512, wmh, wml, 512, bmu, 512, 0, pmh, pml, 256, 256, 0, 0);
    // VQ fp16 1-term (margin + exact repair protect the argmin)
    fgemm<2><<<dim3(MT, 8), 256, SMEM_F>>>(pmh, pml, 256, ebh, ebl, 256, en, 256, 0, 0, 0, 0, NKC, tb, ts);
    combine_kernel<<<512, 256>>>();
    // exact fp32 repair of near-tie rows
    rgather_kernel<<<CAP / 8, 256>>>(x, c);
    gemm2<0><<<dim3(RT, 2), 256, SMEM_BYTES>>>(rx, NF, rc, 2 * NF, W1, b1, rh1, NH, 0, rcnt);
    gemm2<0><<<dim3(RT, 2), 256, SMEM_BYTES>>>(rh1, NH, 0, NH, W2, b2, rh2, NH, 0, rcnt);
    gemm2<0><<<dim3(RT, 2), 256, SMEM_BYTES>>>(rh2, NH, 0, NH, W3, b3, rh1, NH, 0, rcnt);
    gemm2<1><<<dim3(RT, 1), 256, SMEM_BYTES>>>(rh1, NH, 0, NH, Wmu, bmu, rmu, NL, 0, rcnt);
    gemm2<2><<<dim3(RT, 4), 256, SMEM_BYTES>>>(rmu, NL, 0, NL, embed, en, 0, NKC, rkeys, rcnt);
    rscatter_kernel<<<CAP / 256, 256>>>();
    // gather + decoder
    vq_gather_kernel<<<NB / 8, 256>>>(pmh, pml, ebh, ebl, pah, pal);
    fgemm<0><<<dim3(MT, 4), 256, SMEM_F>>>(pah, pal, 544, w4h, w4l, 544, b4, 544, 0, pch, pcl, 512, 512, 0, 0);
    fgemm<0><<<dim3(MT, 4), 256, SMEM_F>>>(pch, pcl, 512, w5h, w5l, 512, b5, 512, 0, pbh, pbl, 512, 512, 0, 0);
    fgemm<0><<<dim3(MT, 4), 256, SMEM_F>>>(pbh, pbl, 512, w6h, w6l, 512, b6, 512, 0, pch, pcl, 512, 512, 0, 0);
    fgemm<1><<<dim3(MT, 3), 256, SMEM_F>>>(pch, pcl, 512, woh, wol, 512, bo, 512, out, 0, 0, NF, NF, 0, 0);
    finalize_kernel<<<1, 256>>>(out);
}

// round 12
// speedup vs baseline: 1.1203x; 1.1203x over previous
#include <cuda_runtime.h>
#include <cuda_fp16.h>
#include <math.h>
#include <stdint.h>

#define NB 131072
#define NH 512
#define NL 256
#define NKC 1024
#define NF 267
#define CAP 65536
#define KTILE 32
#define TILE_F (KTILE * 256)
#define SMEM_BYTES (2 * 2 * TILE_F * 4)

typedef unsigned long long u64;
typedef unsigned int u32;

// ---------------- scratch ----------------
__device__ float  g_enorm[NKC];
__device__ u64    g_key[NB];
__device__ u64    g_tb[(size_t)NB * 8];
__device__ u64    g_ts[(size_t)NB * 8];
__device__ int    g_counts[NKC];
__device__ double g_loss;
__device__ int    g_rcount;
__device__ int    g_flag[CAP];
__device__ u64    g_rkeys[CAP];
// repair fp32 buffers
__device__ float  g_rx[(size_t)CAP * NF];
__device__ float  g_rc[(size_t)CAP * NF];
__device__ float  g_rh1[(size_t)CAP * NH];
__device__ float  g_rh2[(size_t)CAP * NH];
__device__ float  g_rmu[(size_t)CAP * NL];
// fp16 activation planes
__device__ __half g_PXh[(size_t)NB * 544];                          // enc in (hi only)
__device__ __half g_PAh[(size_t)NB * 544], g_PAl[(size_t)NB * 544]; // dec in
__device__ __half g_PBh[(size_t)NB * 512], g_PBl[(size_t)NB * 512];
__device__ __half g_PCh[(size_t)NB * 512], g_PCl[(size_t)NB * 512];
__device__ __half g_PMh[(size_t)NB * 256], g_PMl[(size_t)NB * 256];
// fp16 weight planes [Npad][Kpad]
__device__ __half g_w1h[512 * 544], g_w1l[512 * 544];
__device__ __half g_w2h[512 * 512], g_w2l[512 * 512];
__device__ __half g_w3h[512 * 512], g_w3l[512 * 512];
__device__ __half g_wmh[256 * 512], g_wml[256 * 512];
__device__ __half g_w4h[512 * 544], g_w4l[512 * 544];
__device__ __half g_w5h[512 * 512], g_w5l[512 * 512];
__device__ __half g_w6h[512 * 512], g_w6l[512 * 512];
__device__ __half g_woh[384 * 512], g_wol[384 * 512];
__device__ __half g_ebh[1024 * 256], g_ebl[1024 * 256];

#define FFMA2(d, a, b) asm("fma.rn.f32x2 %0, %1, %2, %0;" : "+l"(d) : "l"(a), "l"(b))
__device__ __forceinline__ u64 dupf(float v) {
    u64 r; asm("mov.b64 %0, {%1, %1};" : "=l"(r) : "f"(v)); return r;
}
__device__ __forceinline__ float lof(u64 v) { return __uint_as_float((unsigned)v); }
__device__ __forceinline__ float hif(u64 v) { return __uint_as_float((unsigned)(v >> 32)); }
__device__ __forceinline__ u32 smem_u32(const void* p) {
    u32 a;
    asm("{ .reg .u64 t; cvta.to.shared.u64 t, %1; cvt.u32.u64 %0, t; }" : "=r"(a) : "l"(p));
    return a;
}
__device__ __forceinline__ void ldsm4(u32* r, u32 addr) {
    asm volatile("ldmatrix.sync.aligned.m8n8.x4.shared.b16 {%0,%1,%2,%3}, [%4];"
        : "=r"(r[0]), "=r"(r[1]), "=r"(r[2]), "=r"(r[3]) : "r"(addr));
}
__device__ __forceinline__ void mmah(float* c, const u32* a, u32 b0, u32 b1) {
    asm volatile("mma.sync.aligned.m16n8k16.row.col.f32.f16.f16.f32 "
        "{%0,%1,%2,%3}, {%4,%5,%6,%7}, {%8,%9}, {%0,%1,%2,%3};"
        : "+f"(c[0]), "+f"(c[1]), "+f"(c[2]), "+f"(c[3])
        : "r"(a[0]), "r"(a[1]), "r"(a[2]), "r"(a[3]), "r"(b0), "r"(b1));
}
__device__ __forceinline__ u64 enc_key(float d, int col) {
    unsigned u = __float_as_uint(d);
    u = (u & 0x80000000u) ? ~u : (u | 0x80000000u);
    return ((u64)u << 32) | (unsigned)col;
}
__device__ __forceinline__ float dec_key(u64 k) {
    unsigned u = (unsigned)(k >> 32);
    u = (u & 0x80000000u) ? (u & 0x7FFFFFFFu) : ~u;
    return __uint_as_float(u);
}
__device__ __forceinline__ void mergeBS(u64& b, u64& s, u64 b2, u64 s2) {
    if (b2 < b) { u64 t = b < s2 ? b : s2; b = b2; s = t; }
    else        { if (b2 < s) s = b2; }
}

// ======================= fp32 FFMA2 GEMM (repair path) =====================
template <int MODE>   // 0 relu, 1 linear, 2 VQ argmin
__global__ void __launch_bounds__(256, 1) gemm2(
    const float* __restrict__ A0, int K0,
    const float* __restrict__ A1, int Ktot,
    const float* __restrict__ W, const float* __restrict__ bias,
    float* __restrict__ C, int N, u64* __restrict__ keys,
    const int* __restrict__ cnt)
{
    extern __shared__ float dyn[];
    float* As = dyn;
    float* Ws = dyn + 2 * TILE_F;

    const int tid = threadIdx.x;
    const int tx = tid & 15, ty = tid >> 4;
    const int m0 = blockIdx.x * 128, n0 = blockIdx.y * 256;
    if (cnt) { int n = *cnt; if (n > CAP) n = CAP; if (m0 >= n) return; }
    const int K1 = Ktot - K0;
    const int am = tid >> 1;
    const int ak = (tid & 1) * 16;
    const int nT = (Ktot + KTILE - 1) / KTILE;

    u64 acc[8][8];
#pragma unroll
    for (int i = 0; i < 8; ++i)
#pragma unroll
        for (int j = 0; j < 8; ++j) acc[i][j] = 0ull;

    float  aReg[16];
    float4 bReg[8];

#define LOADA(kt) do {                                                        \
    _Pragma("unroll")                                                         \
    for (int q = 0; q < 16; ++q) {                                            \
        int k = (kt) * KTILE + ak + q;                                        \
        float v = 0.f;                                                        \
        if (k < K0)        v = A0[(size_t)(m0 + am) * K0 + k];                \
        else if (k < Ktot) v = A1[(size_t)(m0 + am) * K1 + (k - K0)];         \
        aReg[q] = v;                                                          \
    } } while (0)

#define LOADB(kt) do {                                                        \
    _Pragma("unroll")                                                         \
    for (int i = 0; i < 8; ++i) {                                             \
        int idx = tid + i * 256;                                              \
        int k = idx >> 6, n4 = (idx & 63) * 4;                                \
        int kg = (kt) * KTILE + k;                                            \
        int ng = n0 + n4;                                                     \
        float4 v = make_float4(0.f, 0.f, 0.f, 0.f);                           \
        if (kg < Ktot && ng < N) v = *(const float4*)&W[(size_t)kg * N + ng]; \
        bReg[i] = v;                                                          \
    } } while (0)

#define STST(p) do {                                                          \
    float* ab = As + (p) * TILE_F;                                            \
    _Pragma("unroll")                                                         \
    for (int q = 0; q < 16; ++q)                                              \
        *(u64*)(ab + (ak + q) * 256 + 2 * am) = dupf(aReg[q]);                \
    float* wb = Ws + (p) * TILE_F;                                            \
    _Pragma("unroll")                                                         \
    for (int i = 0; i < 8; ++i) {                                             \
        int idx = tid + i * 256;                                              \
        *(float4*)(wb + (idx >> 6) * 256 + (idx & 63) * 4) = bReg[i];         \
    } } while (0)

    LOADA(0); LOADB(0);
    STST(0);
    __syncthreads();

    for (int kt = 0; kt < nT; ++kt) {
        const int p = kt & 1;
        if (kt + 1 < nT) { LOADA(kt + 1); LOADB(kt + 1); }
        const float* ab = As + p * TILE_F + ty * 16;
        const float* wb = Ws + p * TILE_F + tx * 4;
#pragma unroll 4
        for (int k = 0; k < KTILE; ++k) {
            u64 a[8], b[8];
            const ulonglong2* ap = (const ulonglong2*)(ab + k * 256);
#pragma unroll
            for (int q = 0; q < 4; ++q) { ulonglong2 t = ap[q]; a[2*q] = t.x; a[2*q+1] = t.y; }
#pragma unroll
            for (int q = 0; q < 4; ++q) {
                ulonglong2 t = *(const ulonglong2*)(wb + k * 256 + q * 64);
                b[2*q] = t.x; b[2*q+1] = t.y;
            }
#pragma unroll
            for (int i = 0; i < 8; ++i)
#pragma unroll
                for (int j = 0; j < 8; ++j) FFMA2(acc[i][j], a[i], b[j]);
        }
        if (kt + 1 < nT) STST((kt + 1) & 1);
        __syncthreads();
    }

    if (MODE == 2) {
        u64* red = (u64*)dyn;
#pragma unroll
        for (int i = 0; i < 8; ++i) {
            u64 best = ~0ull;
#pragma unroll
            for (int j = 0; j < 8; ++j) {
                int c0 = n0 + (j >> 1) * 64 + tx * 4 + (j & 1) * 2;
                u64 k0 = enc_key(bias[c0]     - 2.f * lof(acc[i][j]), c0);
                u64 k1 = enc_key(bias[c0 + 1] - 2.f * hif(acc[i][j]), c0 + 1);
                if (k0 < best) best = k0;
                if (k1 < best) best = k1;
            }
            red[(ty * 8 + i) * 17 + tx] = best;
        }
        __syncthreads();
        if (tid < 128) {
            u64 b = red[tid * 17];
#pragma unroll
            for (int x = 1; x < 16; ++x) { u64 v = red[tid * 17 + x]; if (v < b) b = v; }
            atomicMin(&keys[m0 + tid], b);
        }
        return;
    }

#pragma unroll
    for (int i = 0; i < 8; ++i) {
        size_t row = (size_t)(m0 + ty * 8 + i);
#pragma unroll
        for (int j = 0; j < 8; ++j) {
            int c0 = n0 + (j >> 1) * 64 + tx * 4 + (j & 1) * 2;
            if (c0 < N) {
                float v = lof(acc[i][j]) + bias[c0];
                if (MODE == 0) v = fmaxf(v, 0.f);
                C[row * N + c0] = v;
            }
            if (c0 + 1 < N) {
                float v = hif(acc[i][j]) + bias[c0 + 1];
                if (MODE == 0) v = fmaxf(v, 0.f);
                C[row * N + c0 + 1] = v;
            }
        }
    }
#undef LOADA
#undef LOADB
#undef STST
}

// ======= fp16-plane mma.sync GEMM, cp.async 3-stage ========================
// TERMS: 3 = Ah*Bh+Ah*Bl+Al*Bh | 2 = Ah*Bh+Ah*Bl (A hi only) | 1 = Ah*Bh
// MODE 0: relu -> hi+lo planes | 1: linear -> fp32, N guard | 2: VQ best/2nd
//      4: linear -> hi+lo planes | 5: relu -> hi plane only
#define FSTG 32768
#define SMEM_F (3 * FSTG)

template <int MODE, int TERMS>
__global__ void __launch_bounds__(256, 1) fgemm(
    const __half* __restrict__ Ah, const __half* __restrict__ Al, int lda,
    const __half* __restrict__ Bh, const __half* __restrict__ Bl, int ldb,
    const float* __restrict__ bias, int Ktot,
    float* __restrict__ outF, __half* __restrict__ outH, __half* __restrict__ outL,
    int ldo, int N, u64* __restrict__ tb, u64* __restrict__ ts)
{
    extern __shared__ char smraw[];
    const u32 smem = smem_u32(smraw);

    const int tid = threadIdx.x;
    const int lane = tid & 31, wid = tid >> 5;
    const int wm = (wid >> 1) * 32, wn = (wid & 1) * 64;
    const int g = lane >> 2, tg = lane & 3;
    const int m0 = blockIdx.x * 128, n0 = blockIdx.y * 128;
    const int nT = Ktot >> 5;

    const int lx = lane & 7;
    const int mA = wm + lx + ((lane & 8) ? 8 : 0);
    const int cA = (lane >> 4) & 1;
    const int nB = wn + lx + ((lane & 16) ? 8 : 0);
    const int cB = (lane >> 3) & 1;

    float acc[2][8][4];
#pragma unroll
    for (int mt = 0; mt < 2; ++mt)
#pragma unroll
        for (int j = 0; j < 8; ++j)
#pragma unroll
            for (int q = 0; q < 4; ++q) acc[mt][j][q] = 0.f;

#define ISSUE(kt) do {                                                         \
    u32 st = smem + ((kt) % 3) * FSTG;                                         \
    _Pragma("unroll")                                                          \
    for (int i = 0; i < 4; ++i) {                                              \
        int idx = tid + i * 256; int m = idx >> 3, cc = idx & 7;               \
        if (TERMS < 3 && cc >= 4) continue;                                    \
        const __half* src = (cc < 4 ? Ah : Al)                                 \
            + (size_t)(m0 + m) * lda + (kt) * 32 + (cc & 3) * 8;               \
        u32 dst = st + m * 128 + ((cc ^ (m & 7)) << 4);                        \
        asm volatile("cp.async.ca.shared.global [%0], [%1], 16;"               \
                     :: "r"(dst), "l"(src));                                   \
    }                                                                          \
    _Pragma("unroll")                                                          \
    for (int i = 0; i < 4; ++i) {                                              \
        int idx = tid + i * 256; int n = idx >> 3, cc = idx & 7;               \
        if (TERMS < 2 && cc >= 4) continue;                                    \
        const __half* src = (cc < 4 ? Bh : Bl)                                 \
            + (size_t)(n0 + n) * ldb + (kt) * 32 + (cc & 3) * 8;               \
        u32 dst = st + 16384 + n * 128 + ((cc ^ (n & 7)) << 4);                \
        asm volatile("cp.async.ca.shared.global [%0], [%1], 16;"               \
                     :: "r"(dst), "l"(src));                                   \
    }                                                                          \
    asm volatile("cp.async.commit_group;"); } while (0)

    ISSUE(0); ISSUE(1);

    for (int kt = 0; kt < nT; ++kt) {
        if (kt + 1 < nT) asm volatile("cp.async.wait_group 1;");
        else             asm volatile("cp.async.wait_group 0;");
        __syncthreads();

        const u32 Abase = smem + (kt % 3) * FSTG;
        const u32 Bbase = Abase + 16384;
#pragma unroll
        for (int s = 0; s < 2; ++s) {
            u32 ah[2][4], al[2][4];
#pragma unroll
            for (int mt = 0; mt < 2; ++mt) {
                u32 rowa = Abase + (mA + mt * 16) * 128;
                int ch = 2 * s + cA;
                ldsm4(ah[mt], rowa + ((ch ^ lx) << 4));
                if (TERMS == 3) ldsm4(al[mt], rowa + (((ch + 4) ^ lx) << 4));
            }
            u32 bh[4][4], bl[4][4];
#pragma unroll
            for (int jp = 0; jp < 4; ++jp) {
                u32 rowb = Bbase + (nB + jp * 16) * 128;
                int ch = 2 * s + cB;
                ldsm4(bh[jp], rowb + ((ch ^ lx) << 4));
                if (TERMS >= 2) ldsm4(bl[jp], rowb + (((ch + 4) ^ lx) << 4));
            }
#pragma unroll
            for (int mt = 0; mt < 2; ++mt)
#pragma unroll
                for (int jp = 0; jp < 4; ++jp)
#pragma unroll
                    for (int jj = 0; jj < 2; ++jj) {
                        float* a = acc[mt][jp * 2 + jj];
                        mmah(a, ah[mt], bh[jp][2*jj], bh[jp][2*jj+1]);
                        if (TERMS >= 2) mmah(a, ah[mt], bl[jp][2*jj], bl[jp][2*jj+1]);
                        if (TERMS == 3) mmah(a, al[mt], bh[jp][2*jj], bh[jp][2*jj+1]);
                    }
        }
        if (kt + 2 < nT) ISSUE(kt + 2);
    }
#undef ISSUE

    if (MODE == 2) {
        __syncthreads();
        u64* pb = (u64*)smraw;          // [128][8]
        u64* ps = pb + 128 * 8;
        const int slot = (wid & 1) * 4 + tg;
#pragma unroll
        for (int mt = 0; mt < 2; ++mt)
#pragma unroll
            for (int dq = 0; dq < 2; ++dq) {
                int rl = wm + mt * 16 + g + dq * 8;
                u64 b = ~0ull, s = ~0ull;
#pragma unroll
                for (int j = 0; j < 8; ++j)
#pragma unroll
                    for (int c01 = 0; c01 < 2; ++c01) {
                        int col = n0 + wn + j * 8 + 2 * tg + c01;
                        u64 k = enc_key(bias[col] - 2.f * acc[mt][j][dq * 2 + c01], col);
                        if (k < b) { s = b; b = k; } else if (k < s) s = k;
                    }
                pb[rl * 8 + slot] = b;
                ps[rl * 8 + slot] = s;
            }
        __syncthreads();
        if (tid < 128) {
            u64 b = pb[tid * 8], s = ps[tid * 8];
#pragma unroll
            for (int k = 1; k < 8; ++k) mergeBS(b, s, pb[tid * 8 + k], ps[tid * 8 + k]);
            tb[(size_t)(m0 + tid) * 8 + blockIdx.y] = b;
            ts[(size_t)(m0 + tid) * 8 + blockIdx.y] = s;
        }
        return;
    }

#pragma unroll
    for (int mt = 0; mt < 2; ++mt) {
        int r0 = m0 + wm + mt * 16 + g;
#pragma unroll
        for (int j = 0; j < 8; ++j) {
            int c0 = n0 + wn + j * 8 + 2 * tg;
            if (MODE == 0 || MODE == 4 || MODE == 5) {
                float b0 = bias[c0], b1 = bias[c0 + 1];
                float v0 = acc[mt][j][0] + b0, v1 = acc[mt][j][1] + b1;
                float v2 = acc[mt][j][2] + b0, v3 = acc[mt][j][3] + b1;
                if (MODE != 4) {
                    v0 = fmaxf(v0, 0.f); v1 = fmaxf(v1, 0.f);
                    v2 = fmaxf(v2, 0.f); v3 = fmaxf(v3, 0.f);
                }
                __half h0 = __float2half_rn(v0), h1 = __float2half_rn(v1);
                __half h2 = __float2half_rn(v2), h3 = __float2half_rn(v3);
                *(__half2*)(outH + (size_t)r0 * ldo + c0) = __halves2half2(h0, h1);
                *(__half2*)(outH + (size_t)(r0 + 8) * ldo + c0) = __halves2half2(h2, h3);
                if (MODE != 5) {
                    *(__half2*)(outL + (size_t)r0 * ldo + c0) = __halves2half2(
                        __float2half_rn(v0 - __half2float(h0)),
                        __float2half_rn(v1 - __half2float(h1)));
                    *(__half2*)(outL + (size_t)(r0 + 8) * ldo + c0) = __halves2half2(
                        __float2half_rn(v2 - __half2float(h2)),
                        __float2half_rn(v3 - __half2float(h3)));
                }
            } else {
                float b0 = (c0 < N) ? bias[c0] : 0.f;
                float b1 = (c0 + 1 < N) ? bias[c0 + 1] : 0.f;
                if (c0 < N) {
                    outF[(size_t)r0 * ldo + c0]       = acc[mt][j][0] + b0;
                    outF[(size_t)(r0 + 8) * ldo + c0] = acc[mt][j][2] + b0;
                }
                if (c0 + 1 < N) {
                    outF[(size_t)r0 * ldo + c0 + 1]       = acc[mt][j][1] + b1;
                    outF[(size_t)(r0 + 8) * ldo + c0 + 1] = acc[mt][j][3] + b1;
                }
            }
        }
    }
}

// ======================= prep / combine / repair kernels ===================
__global__ void init_kernel() {
    int t = blockIdx.x * 256 + threadIdx.x;
    if (t < NKC) g_counts[t] = 0;
    if (t < CAP) g_rkeys[t] = ~0ull;
    if (t == 0) { g_loss = 0.0; g_rcount = 0; }
}
__global__ void enorm_kernel(const float* __restrict__ e) {
    int k = blockIdx.x * 256 + threadIdx.x;
    float s = 0.f;
    for (int l = 0; l < NL; ++l) { float v = e[(size_t)l * NKC + k]; s += v * v; }
    g_enorm[k] = s;
}
__global__ void wsplit_kernel(const float* __restrict__ W, int K, int N, int Kpad,
                              __half* __restrict__ H, __half* __restrict__ L) {
    int n = blockIdx.x;
    int k = blockIdx.y * 256 + threadIdx.x;
    if (k >= Kpad) return;
    float v = (k < K && n < N) ? W[(size_t)k * N + n] : 0.f;
    __half h = __float2half_rn(v);
    size_t o = (size_t)n * Kpad + k;
    H[o] = h;
    L[o] = __float2half_rn(v - __half2float(h));
}
__global__ void xcsplit_kernel(const float* __restrict__ x, const float* __restrict__ c,
                               __half* __restrict__ H) {
    size_t r = blockIdx.x; int j = threadIdx.x;
    float v = 0.f;
    if (j < NF) v = x[r * NF + j];
    else if (j < 2 * NF) v = c[r * NF + j - NF];
    H[r * 544 + j] = __float2half_rn(v);
}
__global__ void csplit_kernel(const float* __restrict__ c,
                              __half* __restrict__ H, __half* __restrict__ L) {
    size_t r = blockIdx.x; int j = threadIdx.x;
    float v = (j < NF) ? c[r * NF + j] : 0.f;
    __half h = __float2half_rn(v);
    H[r * 544 + 256 + j] = h;
    L[r * 544 + 256 + j] = __float2half_rn(v - __half2float(h));
}
__global__ void combine_kernel() {
    int row = blockIdx.x * 256 + threadIdx.x;
    u64 b = g_tb[(size_t)row * 8], s = g_ts[(size_t)row * 8];
#pragma unroll
    for (int t = 1; t < 8; ++t) mergeBS(b, s, g_tb[(size_t)row * 8 + t], g_ts[(size_t)row * 8 + t]);
    g_key[row] = b;
    float d1 = dec_key(b), d2 = dec_key(s);
    if (d2 - d1 < 0.25f + 1e-3f * fabsf(d1)) {
        int pos = atomicAdd(&g_rcount, 1);
        if (pos < CAP) g_flag[pos] = row;
    }
}
__global__ void rgather_kernel(const float* __restrict__ x, const float* __restrict__ c) {
    int n = g_rcount; if (n > CAP) n = CAP;
    int i = blockIdx.x * 8 + (threadIdx.x >> 5);
    if (i >= n) return;
    int lane = threadIdx.x & 31;
    size_t row = (size_t)g_flag[i];
    for (int j = lane; j < NF; j += 32) {
        g_rx[(size_t)i * NF + j] = x[row * NF + j];
        g_rc[(size_t)i * NF + j] = c[row * NF + j];
    }
}
__global__ void rscatter_kernel() {
    int n = g_rcount; if (n > CAP) n = CAP;
    int i = blockIdx.x * 256 + threadIdx.x;
    if (i < n) g_key[g_flag[i]] = g_rkeys[i];
}
__global__ void vq_gather_kernel(const __half* __restrict__ pmh, const __half* __restrict__ pml,
                                 const __half* __restrict__ ebh, const __half* __restrict__ ebl,
                                 __half* __restrict__ H, __half* __restrict__ L) {
    __shared__ float s_ls[8];
    const int wid = threadIdx.x >> 5, lane = threadIdx.x & 31;
    const size_t row = (size_t)blockIdx.x * 8 + wid;
    const int ind = (int)(g_key[row] & 0xFFFFFFFFull);
    if (lane == 0) atomicAdd(&g_counts[ind], 1);
    float ls = 0.f;
#pragma unroll
    for (int i = 0; i < 8; ++i) {
        int dim = i * 32 + lane;
        __half qh = ebh[(size_t)ind * 256 + dim];
        __half ql = ebl[(size_t)ind * 256 + dim];
        float qv = __half2float(qh) + __half2float(ql);
        float mv = __half2float(pmh[row * 256 + dim]) + __half2float(pml[row * 256 + dim]);
        H[row * 544 + dim] = qh;
        L[row * 544 + dim] = ql;
        float d = qv - mv;
        ls += d * d;
    }
#pragma unroll
    for (int s = 16; s > 0; s >>= 1) ls += __shfl_down_sync(0xFFFFFFFF, ls, s);
    if (lane == 0) s_ls[wid] = ls;
    __syncthreads();
    if (threadIdx.x == 0) {
        double t = 0.0;
        for (int w = 0; w < 8; ++w) t += (double)s_ls[w];
        atomicAdd(&g_loss, t);
    }
}
__global__ void finalize_kernel(float* __restrict__ out) {
    __shared__ double sh[256];
    int t = threadIdx.x;
    double e = 0.0;
    for (int k = t; k < NKC; k += 256) {
        double p = (double)g_counts[k] / (double)NB;
        e += p * log(p + 1e-10);
    }
    sh[t] = e;
    __syncthreads();
    for (int s = 128; s > 0; s >>= 1) { if (t < s) sh[t] += sh[t + s]; __syncthreads(); }
    if (t == 0) {
        out[(size_t)NB * NF]     = (float)(g_loss / ((double)NB * (double)NL));
        out[(size_t)NB * NF + 1] = (float)exp(-sh[0]);
    }
}

// ======================= launch ===========================================
extern "C" void kernel_launch(void* const* d_in, const int* in_sizes, int n_in,
                              void* d_out, int out_size)
{
    const float* x     = (const float*)d_in[0];
    const float* c     = (const float*)d_in[1];
    const float* W1    = (const float*)d_in[2];
    const float* b1    = (const float*)d_in[3];
    const float* W2    = (const float*)d_in[4];
    const float* b2    = (const float*)d_in[5];
    const float* W3    = (const float*)d_in[6];
    const float* b3    = (const float*)d_in[7];
    const float* Wmu   = (const float*)d_in[8];
    const float* bmu   = (const float*)d_in[9];
    const float* W4    = (const float*)d_in[10];
    const float* b4    = (const float*)d_in[11];
    const float* W5    = (const float*)d_in[12];
    const float* b5    = (const float*)d_in[13];
    const float* W6    = (const float*)d_in[14];
    const float* b6    = (const float*)d_in[15];
    const float* Wo    = (const float*)d_in[16];
    const float* bo    = (const float*)d_in[17];
    const float* embed = (const float*)d_in[18];
    float* out = (float*)d_out;

    float *en, *rx, *rc, *rh1, *rh2, *rmu;
    u64 *keys, *tb, *ts, *rkeys;
    int* rcnt;
    __half *pxh, *pah, *pal, *pbh, *pbl, *pch, *pcl, *pmh, *pml;
    __half *w1h, *w1l, *w2h, *w2l, *w3h, *w3l, *wmh, *wml;
    __half *w4h, *w4l, *w5h, *w5l, *w6h, *w6l, *woh, *wol, *ebh, *ebl;
    cudaGetSymbolAddress((void**)&en,   g_enorm);
    cudaGetSymbolAddress((void**)&keys, g_key);
    cudaGetSymbolAddress((void**)&tb,   g_tb);
    cudaGetSymbolAddress((void**)&ts,   g_ts);
    cudaGetSymbolAddress((void**)&rkeys, g_rkeys);
    cudaGetSymbolAddress((void**)&rcnt, g_rcount);
    cudaGetSymbolAddress((void**)&rx,   g_rx);
    cudaGetSymbolAddress((void**)&rc,   g_rc);
    cudaGetSymbolAddress((void**)&rh1,  g_rh1);
    cudaGetSymbolAddress((void**)&rh2,  g_rh2);
    cudaGetSymbolAddress((void**)&rmu,  g_rmu);
    cudaGetSymbolAddress((void**)&pxh,  g_PXh);
    cudaGetSymbolAddress((void**)&pah,  g_PAh);
    cudaGetSymbolAddress((void**)&pal,  g_PAl);
    cudaGetSymbolAddress((void**)&pbh,  g_PBh);
    cudaGetSymbolAddress((void**)&pbl,  g_PBl);
    cudaGetSymbolAddress((void**)&pch,  g_PCh);
    cudaGetSymbolAddress((void**)&pcl,  g_PCl);
    cudaGetSymbolAddress((void**)&pmh,  g_PMh);
    cudaGetSymbolAddress((void**)&pml,  g_PMl);
    cudaGetSymbolAddress((void**)&w1h,  g_w1h);  cudaGetSymbolAddress((void**)&w1l, g_w1l);
    cudaGetSymbolAddress((void**)&w2h,  g_w2h);  cudaGetSymbolAddress((void**)&w2l, g_w2l);
    cudaGetSymbolAddress((void**)&w3h,  g_w3h);  cudaGetSymbolAddress((void**)&w3l, g_w3l);
    cudaGetSymbolAddress((void**)&wmh,  g_wmh);  cudaGetSymbolAddress((void**)&wml, g_wml);
    cudaGetSymbolAddress((void**)&w4h,  g_w4h);  cudaGetSymbolAddress((void**)&w4l, g_w4l);
    cudaGetSymbolAddress((void**)&w5h,  g_w5h);  cudaGetSymbolAddress((void**)&w5l, g_w5l);
    cudaGetSymbolAddress((void**)&w6h,  g_w6h);  cudaGetSymbolAddress((void**)&w6l, g_w6l);
    cudaGetSymbolAddress((void**)&woh,  g_woh);  cudaGetSymbolAddress((void**)&wol, g_wol);
    cudaGetSymbolAddress((void**)&ebh,  g_ebh);  cudaGetSymbolAddress((void**)&ebl, g_ebl);

    cudaFuncSetAttribute(gemm2<0>, cudaFuncAttributeMaxDynamicSharedMemorySize, SMEM_BYTES);
    cudaFuncSetAttribute(gemm2<1>, cudaFuncAttributeMaxDynamicSharedMemorySize, SMEM_BYTES);
    cudaFuncSetAttribute(gemm2<2>, cudaFuncAttributeMaxDynamicSharedMemorySize, SMEM_BYTES);
    cudaFuncSetAttribute((const void*)fgemm<0, 3>, cudaFuncAttributeMaxDynamicSharedMemorySize, SMEM_F);
    cudaFuncSetAttribute((const void*)fgemm<1, 3>, cudaFuncAttributeMaxDynamicSharedMemorySize, SMEM_F);
    cudaFuncSetAttribute((const void*)fgemm<2, 1>, cudaFuncAttributeMaxDynamicSharedMemorySize, SMEM_F);
    cudaFuncSetAttribute((const void*)fgemm<4, 2>, cudaFuncAttributeMaxDynamicSharedMemorySize, SMEM_F);
    cudaFuncSetAttribute((const void*)fgemm<5, 2>, cudaFuncAttributeMaxDynamicSharedMemorySize, SMEM_F);

    const int MT = NB / 128;   // 1024
    const int RT = CAP / 128;  // 512
    init_kernel<<<256, 256>>>();
    enorm_kernel<<<4, 256>>>(embed);
    wsplit_kernel<<<dim3(512, 3), 256>>>(W1, 534, 512, 544, w1h, w1l);
    wsplit_kernel<<<dim3(512, 2), 256>>>(W2, 512, 512, 512, w2h, w2l);
    wsplit_kernel<<<dim3(512, 2), 256>>>(W3, 512, 512, 512, w3h, w3l);
    wsplit_kernel<<<dim3(256, 2), 256>>>(Wmu, 512, 256, 512, wmh, wml);
    wsplit_kernel<<<dim3(512, 3), 256>>>(W4, 523, 512, 544, w4h, w4l);
    wsplit_kernel<<<dim3(512, 2), 256>>>(W5, 512, 512, 512, w5h, w5l);
    wsplit_kernel<<<dim3(512, 2), 256>>>(W6, 512, 512, 512, w6h, w6l);
    wsplit_kernel<<<dim3(384, 2), 256>>>(Wo, 512, 267, 512, woh, wol);
    wsplit_kernel<<<dim3(1024, 1), 256>>>(embed, 256, 1024, 256, ebh, ebl);
    xcsplit_kernel<<<NB, 544>>>(x, c, pxh);
    csplit_kernel<<<NB, 288>>>(c, pah, pal);

    // encoder: 2-term (activations hi-only; VQ argmin protected by margin+repair)
    fgemm<5, 2><<<dim3(MT, 4), 256, SMEM_F>>>(pxh, pxh, 544, w1h, w1l, 544, b1, 544, 0, pbh, 0, 512, 512, 0, 0);
    fgemm<5, 2><<<dim3(MT, 4), 256, SMEM_F>>>(pbh, pbh, 512, w2h, w2l, 512, b2, 512, 0, pch, 0, 512, 512, 0, 0);
    fgemm<5, 2><<<dim3(MT, 4), 256, SMEM_F>>>(pch, pch, 512, w3h, w3l, 512, b3, 512, 0, pbh, 0, 512, 512, 0, 0);
    fgemm<4, 2><<<dim3(MT, 2), 256, SMEM_F>>>(pbh, pbh, 512, wmh, wml, 512, bmu, 512, 0, pmh, pml, 256, 256, 0, 0);
    // VQ 1-term
    fgemm<2, 1><<<dim3(MT, 8), 256, SMEM_F>>>(pmh, pmh, 256, ebh, ebh, 256, en, 256, 0, 0, 0, 0, NKC, tb, ts);
    combine_kernel<<<512, 256>>>();
    // exact fp32 repair of near-tie rows
    rgather_kernel<<<CAP / 8, 256>>>(x, c);
    gemm2<0><<<dim3(RT, 2), 256, SMEM_BYTES>>>(rx, NF, rc, 2 * NF, W1, b1, rh1, NH, 0, rcnt);
    gemm2<0><<<dim3(RT, 2), 256, SMEM_BYTES>>>(rh1, NH, 0, NH, W2, b2, rh2, NH, 0, rcnt);
    gemm2<0><<<dim3(RT, 2), 256, SMEM_BYTES>>>(rh2, NH, 0, NH, W3, b3, rh1, NH, 0, rcnt);
    gemm2<1><<<dim3(RT, 1), 256, SMEM_BYTES>>>(rh1, NH, 0, NH, Wmu, bmu, rmu, NL, 0, rcnt);
    gemm2<2><<<dim3(RT, 4), 256, SMEM_BYTES>>>(rmu, NL, 0, NL, embed, en, 0, NKC, rkeys, rcnt);
    rscatter_kernel<<<CAP / 256, 256>>>();
    // gather + decoder (3-term, exact-grade)
    vq_gather_kernel<<<NB / 8, 256>>>(pmh, pml, ebh, ebl, pah, pal);
    fgemm<0, 3><<<dim3(MT, 4), 256, SMEM_F>>>(pah, pal, 544, w4h, w4l, 544, b4, 544, 0, pch, pcl, 512, 512, 0, 0);
    fgemm<0, 3><<<dim3(MT, 4), 256, SMEM_F>>>(pch, pcl, 512, w5h, w5l, 512, b5, 512, 0, pbh, pbl, 512, 512, 0, 0);
    fgemm<0, 3><<<dim3(MT, 4), 256, SMEM_F>>>(pbh, pbl, 512, w6h, w6l, 512, b6, 512, 0, pch, pcl, 512, 512, 0, 0);
    fgemm<1, 3><<<dim3(MT, 3), 256, SMEM_F>>>(pch, pcl, 512, woh, wol, 512, bo, 512, out, 0, 0, NF, NF, 0, 0);
    finalize_kernel<<<1, 256>>>(out);
}

// round 15
// speedup vs baseline: 1.2968x; 1.1575x over previous
#include <cuda_runtime.h>
#include <cuda_fp16.h>
#include <math.h>
#include <stdint.h>

#define NB 131072
#define NH 512
#define NL 256
#define NKC 1024
#define NF 267
#define CAP 65536
#define KTILE 32
#define TILE_F (KTILE * 256)
#define SMEM_BYTES (2 * 2 * TILE_F * 4)

typedef unsigned long long u64;
typedef unsigned int u32;

// ---------------- scratch ----------------
__device__ float  g_enorm[NKC];
__device__ u64    g_key[NB];
__device__ u64    g_tb[(size_t)NB * 8];
__device__ u64    g_ts[(size_t)NB * 8];
__device__ int    g_counts[NKC];
__device__ double g_loss;
__device__ int    g_rcount;
__device__ int    g_flag[CAP];
__device__ u64    g_rkeys[CAP];
// repair fp32 buffers
__device__ float  g_rx[(size_t)CAP * NF];
__device__ float  g_rc[(size_t)CAP * NF];
__device__ float  g_rh1[(size_t)CAP * NH];
__device__ float  g_rh2[(size_t)CAP * NH];
__device__ float  g_rmu[(size_t)CAP * NL];
// fp16 activation planes (hi-only everywhere except mu which keeps lo for loss)
__device__ __half g_PXh[(size_t)NB * 544];
__device__ __half g_PAh[(size_t)NB * 544];
__device__ __half g_PBh[(size_t)NB * 512];
__device__ __half g_PCh[(size_t)NB * 512];
__device__ __half g_PMh[(size_t)NB * 256], g_PMl[(size_t)NB * 256];
// fp16 weight planes [Npad][Kpad]
__device__ __half g_w1h[512 * 544], g_w1l[512 * 544];
__device__ __half g_w2h[512 * 512], g_w2l[512 * 512];
__device__ __half g_w3h[512 * 512], g_w3l[512 * 512];
__device__ __half g_wmh[256 * 512], g_wml[256 * 512];
__device__ __half g_w4h[512 * 544], g_w4l[512 * 544];
__device__ __half g_w5h[512 * 512], g_w5l[512 * 512];
__device__ __half g_w6h[512 * 512], g_w6l[512 * 512];
__device__ __half g_woh[384 * 512], g_wol[384 * 512];
__device__ __half g_ebh[1024 * 256], g_ebl[1024 * 256];

#define FFMA2(d, a, b) asm("fma.rn.f32x2 %0, %1, %2, %0;" : "+l"(d) : "l"(a), "l"(b))
__device__ __forceinline__ u64 dupf(float v) {
    u64 r; asm("mov.b64 %0, {%1, %1};" : "=l"(r) : "f"(v)); return r;
}
__device__ __forceinline__ float lof(u64 v) { return __uint_as_float((unsigned)v); }
__device__ __forceinline__ float hif(u64 v) { return __uint_as_float((unsigned)(v >> 32)); }
__device__ __forceinline__ u32 smem_u32(const void* p) {
    u32 a;
    asm("{ .reg .u64 t; cvta.to.shared.u64 t, %1; cvt.u32.u64 %0, t; }" : "=r"(a) : "l"(p));
    return a;
}
__device__ __forceinline__ void ldsm4(u32* r, u32 addr) {
    asm volatile("ldmatrix.sync.aligned.m8n8.x4.shared.b16 {%0,%1,%2,%3}, [%4];"
        : "=r"(r[0]), "=r"(r[1]), "=r"(r[2]), "=r"(r[3]) : "r"(addr));
}
__device__ __forceinline__ void mmah(float* c, const u32* a, u32 b0, u32 b1) {
    asm volatile("mma.sync.aligned.m16n8k16.row.col.f32.f16.f16.f32 "
        "{%0,%1,%2,%3}, {%4,%5,%6,%7}, {%8,%9}, {%0,%1,%2,%3};"
        : "+f"(c[0]), "+f"(c[1]), "+f"(c[2]), "+f"(c[3])
        : "r"(a[0]), "r"(a[1]), "r"(a[2]), "r"(a[3]), "r"(b0), "r"(b1));
}
__device__ __forceinline__ u64 enc_key(float d, int col) {
    unsigned u = __float_as_uint(d);
    u = (u & 0x80000000u) ? ~u : (u | 0x80000000u);
    return ((u64)u << 32) | (unsigned)col;
}
__device__ __forceinline__ float dec_key(u64 k) {
    unsigned u = (unsigned)(k >> 32);
    u = (u & 0x80000000u) ? (u & 0x7FFFFFFFu) : ~u;
    return __uint_as_float(u);
}
__device__ __forceinline__ void mergeBS(u64& b, u64& s, u64 b2, u64 s2) {
    if (b2 < b) { u64 t = b < s2 ? b : s2; b = b2; s = t; }
    else        { if (b2 < s) s = b2; }
}

// ======================= fp32 FFMA2 GEMM (repair path) =====================
template <int MODE>   // 0 relu, 1 linear, 2 VQ argmin
__global__ void __launch_bounds__(256, 1) gemm2(
    const float* __restrict__ A0, int K0,
    const float* __restrict__ A1, int Ktot,
    const float* __restrict__ W, const float* __restrict__ bias,
    float* __restrict__ C, int N, u64* __restrict__ keys,
    const int* __restrict__ cnt)
{
    extern __shared__ float dyn[];
    float* As = dyn;
    float* Ws = dyn + 2 * TILE_F;

    const int tid = threadIdx.x;
    const int tx = tid & 15, ty = tid >> 4;
    const int m0 = blockIdx.x * 128, n0 = blockIdx.y * 256;
    if (cnt) { int n = *cnt; if (n > CAP) n = CAP; if (m0 >= n) return; }
    const int K1 = Ktot - K0;
    const int am = tid >> 1;
    const int ak = (tid & 1) * 16;
    const int nT = (Ktot + KTILE - 1) / KTILE;

    u64 acc[8][8];
#pragma unroll
    for (int i = 0; i < 8; ++i)
#pragma unroll
        for (int j = 0; j < 8; ++j) acc[i][j] = 0ull;

    float  aReg[16];
    float4 bReg[8];

#define LOADA(kt) do {                                                        \
    _Pragma("unroll")                                                         \
    for (int q = 0; q < 16; ++q) {                                            \
        int k = (kt) * KTILE + ak + q;                                        \
        float v = 0.f;                                                        \
        if (k < K0)        v = A0[(size_t)(m0 + am) * K0 + k];                \
        else if (k < Ktot) v = A1[(size_t)(m0 + am) * K1 + (k - K0)];         \
        aReg[q] = v;                                                          \
    } } while (0)

#define LOADB(kt) do {                                                        \
    _Pragma("unroll")                                                         \
    for (int i = 0; i < 8; ++i) {                                             \
        int idx = tid + i * 256;                                              \
        int k = idx >> 6, n4 = (idx & 63) * 4;                                \
        int kg = (kt) * KTILE + k;                                            \
        int ng = n0 + n4;                                                     \
        float4 v = make_float4(0.f, 0.f, 0.f, 0.f);                           \
        if (kg < Ktot && ng < N) v = *(const float4*)&W[(size_t)kg * N + ng]; \
        bReg[i] = v;                                                          \
    } } while (0)

#define STST(p) do {                                                          \
    float* ab = As + (p) * TILE_F;                                            \
    _Pragma("unroll")                                                         \
    for (int q = 0; q < 16; ++q)                                              \
        *(u64*)(ab + (ak + q) * 256 + 2 * am) = dupf(aReg[q]);                \
    float* wb = Ws + (p) * TILE_F;                                            \
    _Pragma("unroll")                                                         \
    for (int i = 0; i < 8; ++i) {                                             \
        int idx = tid + i * 256;                                              \
        *(float4*)(wb + (idx >> 6) * 256 + (idx & 63) * 4) = bReg[i];         \
    } } while (0)

    LOADA(0); LOADB(0);
    STST(0);
    __syncthreads();

    for (int kt = 0; kt < nT; ++kt) {
        const int p = kt & 1;
        if (kt + 1 < nT) { LOADA(kt + 1); LOADB(kt + 1); }
        const float* ab = As + p * TILE_F + ty * 16;
        const float* wb = Ws + p * TILE_F + tx * 4;
#pragma unroll 4
        for (int k = 0; k < KTILE; ++k) {
            u64 a[8], b[8];
            const ulonglong2* ap = (const ulonglong2*)(ab + k * 256);
#pragma unroll
            for (int q = 0; q < 4; ++q) { ulonglong2 t = ap[q]; a[2*q] = t.x; a[2*q+1] = t.y; }
#pragma unroll
            for (int q = 0; q < 4; ++q) {
                ulonglong2 t = *(const ulonglong2*)(wb + k * 256 + q * 64);
                b[2*q] = t.x; b[2*q+1] = t.y;
            }
#pragma unroll
            for (int i = 0; i < 8; ++i)
#pragma unroll
                for (int j = 0; j < 8; ++j) FFMA2(acc[i][j], a[i], b[j]);
        }
        if (kt + 1 < nT) STST((kt + 1) & 1);
        __syncthreads();
    }

    if (MODE == 2) {
        u64* red = (u64*)dyn;
#pragma unroll
        for (int i = 0; i < 8; ++i) {
            u64 best = ~0ull;
#pragma unroll
            for (int j = 0; j < 8; ++j) {
                int c0 = n0 + (j >> 1) * 64 + tx * 4 + (j & 1) * 2;
                u64 k0 = enc_key(bias[c0]     - 2.f * lof(acc[i][j]), c0);
                u64 k1 = enc_key(bias[c0 + 1] - 2.f * hif(acc[i][j]), c0 + 1);
                if (k0 < best) best = k0;
                if (k1 < best) best = k1;
            }
            red[(ty * 8 + i) * 17 + tx] = best;
        }
        __syncthreads();
        if (tid < 128) {
            u64 b = red[tid * 17];
#pragma unroll
            for (int x = 1; x < 16; ++x) { u64 v = red[tid * 17 + x]; if (v < b) b = v; }
            atomicMin(&keys[m0 + tid], b);
        }
        return;
    }

#pragma unroll
    for (int i = 0; i < 8; ++i) {
        size_t row = (size_t)(m0 + ty * 8 + i);
#pragma unroll
        for (int j = 0; j < 8; ++j) {
            int c0 = n0 + (j >> 1) * 64 + tx * 4 + (j & 1) * 2;
            if (c0 < N) {
                float v = lof(acc[i][j]) + bias[c0];
                if (MODE == 0) v = fmaxf(v, 0.f);
                C[row * N + c0] = v;
            }
            if (c0 + 1 < N) {
                float v = hif(acc[i][j]) + bias[c0 + 1];
                if (MODE == 0) v = fmaxf(v, 0.f);
                C[row * N + c0 + 1] = v;
            }
        }
    }
#undef LOADA
#undef LOADB
#undef STST
}

// ======= fp16-plane mma.sync GEMM, cp.async 3-stage ========================
// TERMS: 3 = Ah*Bh+Ah*Bl+Al*Bh | 2 = Ah*Bh+Ah*Bl (A hi only) | 1 = Ah*Bh
// MODE 1: linear -> fp32, N guard | 2: VQ best/2nd
//      4: linear -> hi+lo planes | 5: relu -> hi plane only
#define FSTG 32768
#define SMEM_F (3 * FSTG)

template <int MODE, int TERMS>
__global__ void __launch_bounds__(256, 1) fgemm(
    const __half* __restrict__ Ah, const __half* __restrict__ Al, int lda,
    const __half* __restrict__ Bh, const __half* __restrict__ Bl, int ldb,
    const float* __restrict__ bias, int Ktot,
    float* __restrict__ outF, __half* __restrict__ outH, __half* __restrict__ outL,
    int ldo, int N, u64* __restrict__ tb, u64* __restrict__ ts)
{
    extern __shared__ char smraw[];
    const u32 smem = smem_u32(smraw);

    const int tid = threadIdx.x;
    const int lane = tid & 31, wid = tid >> 5;
    const int wm = (wid >> 1) * 32, wn = (wid & 1) * 64;
    const int g = lane >> 2, tg = lane & 3;
    const int m0 = blockIdx.x * 128, n0 = blockIdx.y * 128;
    const int nT = Ktot >> 5;

    const int lx = lane & 7;
    const int mA = wm + lx + ((lane & 8) ? 8 : 0);
    const int cA = (lane >> 4) & 1;
    const int nB = wn + lx + ((lane & 16) ? 8 : 0);
    const int cB = (lane >> 3) & 1;

    float acc[2][8][4];
#pragma unroll
    for (int mt = 0; mt < 2; ++mt)
#pragma unroll
        for (int j = 0; j < 8; ++j)
#pragma unroll
            for (int q = 0; q < 4; ++q) acc[mt][j][q] = 0.f;

#define ISSUE(kt) do {                                                         \
    u32 st = smem + ((kt) % 3) * FSTG;                                         \
    _Pragma("unroll")                                                          \
    for (int i = 0; i < 4; ++i) {                                              \
        int idx = tid + i * 256; int m = idx >> 3, cc = idx & 7;               \
        if (TERMS < 3 && cc >= 4) continue;                                    \
        const __half* src = (cc < 4 ? Ah : Al)                                 \
            + (size_t)(m0 + m) * lda + (kt) * 32 + (cc & 3) * 8;               \
        u32 dst = st + m * 128 + ((cc ^ (m & 7)) << 4);                        \
        asm volatile("cp.async.ca.shared.global [%0], [%1], 16;"               \
                     :: "r"(dst), "l"(src));                                   \
    }                                                                          \
    _Pragma("unroll")                                                          \
    for (int i = 0; i < 4; ++i) {                                              \
        int idx = tid + i * 256; int n = idx >> 3, cc = idx & 7;               \
        if (TERMS < 2 && cc >= 4) continue;                                    \
        const __half* src = (cc < 4 ? Bh : Bl)                                 \
            + (size_t)(n0 + n) * ldb + (kt) * 32 + (cc & 3) * 8;               \
        u32 dst = st + 16384 + n * 128 + ((cc ^ (n & 7)) << 4);                \
        asm volatile("cp.async.ca.shared.global [%0], [%1], 16;"               \
                     :: "r"(dst), "l"(src));                                   \
    }                                                                          \
    asm volatile("cp.async.commit_group;"); } while (0)

    ISSUE(0); ISSUE(1);

    for (int kt = 0; kt < nT; ++kt) {
        if (kt + 1 < nT) asm volatile("cp.async.wait_group 1;");
        else             asm volatile("cp.async.wait_group 0;");
        __syncthreads();

        const u32 Abase = smem + (kt % 3) * FSTG;
        const u32 Bbase = Abase + 16384;
#pragma unroll
        for (int s = 0; s < 2; ++s) {
            u32 ah[2][4], al[2][4];
#pragma unroll
            for (int mt = 0; mt < 2; ++mt) {
                u32 rowa = Abase + (mA + mt * 16) * 128;
                int ch = 2 * s + cA;
                ldsm4(ah[mt], rowa + ((ch ^ lx) << 4));
                if (TERMS == 3) ldsm4(al[mt], rowa + (((ch + 4) ^ lx) << 4));
            }
            u32 bh[4][4], bl[4][4];
#pragma unroll
            for (int jp = 0; jp < 4; ++jp) {
                u32 rowb = Bbase + (nB + jp * 16) * 128;
                int ch = 2 * s + cB;
                ldsm4(bh[jp], rowb + ((ch ^ lx) << 4));
                if (TERMS >= 2) ldsm4(bl[jp], rowb + (((ch + 4) ^ lx) << 4));
            }
#pragma unroll
            for (int mt = 0; mt < 2; ++mt)
#pragma unroll
                for (int jp = 0; jp < 4; ++jp)
#pragma unroll
                    for (int jj = 0; jj < 2; ++jj) {
                        float* a = acc[mt][jp * 2 + jj];
                        mmah(a, ah[mt], bh[jp][2*jj], bh[jp][2*jj+1]);
                        if (TERMS >= 2) mmah(a, ah[mt], bl[jp][2*jj], bl[jp][2*jj+1]);
                        if (TERMS == 3) mmah(a, al[mt], bh[jp][2*jj], bh[jp][2*jj+1]);
                    }
        }
        if (kt + 2 < nT) ISSUE(kt + 2);
    }
#undef ISSUE

    if (MODE == 2) {
        __syncthreads();
        u64* pb = (u64*)smraw;          // [128][8]
        u64* ps = pb + 128 * 8;
        const int slot = (wid & 1) * 4 + tg;
#pragma unroll
        for (int mt = 0; mt < 2; ++mt)
#pragma unroll
            for (int dq = 0; dq < 2; ++dq) {
                int rl = wm + mt * 16 + g + dq * 8;
                u64 b = ~0ull, s = ~0ull;
#pragma unroll
                for (int j = 0; j < 8; ++j)
#pragma unroll
                    for (int c01 = 0; c01 < 2; ++c01) {
                        int col = n0 + wn + j * 8 + 2 * tg + c01;
                        u64 k = enc_key(bias[col] - 2.f * acc[mt][j][dq * 2 + c01], col);
                        if (k < b) { s = b; b = k; } else if (k < s) s = k;
                    }
                pb[rl * 8 + slot] = b;
                ps[rl * 8 + slot] = s;
            }
        __syncthreads();
        if (tid < 128) {
            u64 b = pb[tid * 8], s = ps[tid * 8];
#pragma unroll
            for (int k = 1; k < 8; ++k) mergeBS(b, s, pb[tid * 8 + k], ps[tid * 8 + k]);
            tb[(size_t)(m0 + tid) * 8 + blockIdx.y] = b;
            ts[(size_t)(m0 + tid) * 8 + blockIdx.y] = s;
        }
        return;
    }

#pragma unroll
    for (int mt = 0; mt < 2; ++mt) {
        int r0 = m0 + wm + mt * 16 + g;
#pragma unroll
        for (int j = 0; j < 8; ++j) {
            int c0 = n0 + wn + j * 8 + 2 * tg;
            if (MODE == 4 || MODE == 5) {
                float b0 = bias[c0], b1 = bias[c0 + 1];
                float v0 = acc[mt][j][0] + b0, v1 = acc[mt][j][1] + b1;
                float v2 = acc[mt][j][2] + b0, v3 = acc[mt][j][3] + b1;
                if (MODE != 4) {
                    v0 = fmaxf(v0, 0.f); v1 = fmaxf(v1, 0.f);
                    v2 = fmaxf(v2, 0.f); v3 = fmaxf(v3, 0.f);
                }
                __half h0 = __float2half_rn(v0), h1 = __float2half_rn(v1);
                __half h2 = __float2half_rn(v2), h3 = __float2half_rn(v3);
                *(__half2*)(outH + (size_t)r0 * ldo + c0) = __halves2half2(h0, h1);
                *(__half2*)(outH + (size_t)(r0 + 8) * ldo + c0) = __halves2half2(h2, h3);
                if (MODE == 4) {
                    *(__half2*)(outL + (size_t)r0 * ldo + c0) = __halves2half2(
                        __float2half_rn(v0 - __half2float(h0)),
                        __float2half_rn(v1 - __half2float(h1)));
                    *(__half2*)(outL + (size_t)(r0 + 8) * ldo + c0) = __halves2half2(
                        __float2half_rn(v2 - __half2float(h2)),
                        __float2half_rn(v3 - __half2float(h3)));
                }
            } else {
                float b0 = (c0 < N) ? bias[c0] : 0.f;
                float b1 = (c0 + 1 < N) ? bias[c0 + 1] : 0.f;
                if (c0 < N) {
                    outF[(size_t)r0 * ldo + c0]       = acc[mt][j][0] + b0;
                    outF[(size_t)(r0 + 8) * ldo + c0] = acc[mt][j][2] + b0;
                }
                if (c0 + 1 < N) {
                    outF[(size_t)r0 * ldo + c0 + 1]       = acc[mt][j][1] + b1;
                    outF[(size_t)(r0 + 8) * ldo + c0 + 1] = acc[mt][j][3] + b1;
                }
            }
        }
    }
}

// ======================= prep / combine / repair kernels ===================
__global__ void init_kernel() {
    int t = blockIdx.x * 256 + threadIdx.x;
    if (t < NKC) g_counts[t] = 0;
    if (t < CAP) g_rkeys[t] = ~0ull;
    if (t == 0) { g_loss = 0.0; g_rcount = 0; }
}
__global__ void enorm_kernel(const float* __restrict__ e) {
    int k = blockIdx.x * 256 + threadIdx.x;
    float s = 0.f;
    for (int l = 0; l < NL; ++l) { float v = e[(size_t)l * NKC + k]; s += v * v; }
    g_enorm[k] = s;
}
__global__ void wsplit_kernel(const float* __restrict__ W, int K, int N, int Kpad,
                              __half* __restrict__ H, __half* __restrict__ L) {
    int n = blockIdx.x;
    int k = blockIdx.y * 256 + threadIdx.x;
    if (k >= Kpad) return;
    float v = (k < K && n < N) ? W[(size_t)k * N + n] : 0.f;
    __half h = __float2half_rn(v);
    size_t o = (size_t)n * Kpad + k;
    H[o] = h;
    L[o] = __float2half_rn(v - __half2float(h));
}
__global__ void xcsplit_kernel(const float* __restrict__ x, const float* __restrict__ c,
                               __half* __restrict__ H) {
    size_t r = blockIdx.x; int j = threadIdx.x;
    float v = 0.f;
    if (j < NF) v = x[r * NF + j];
    else if (j < 2 * NF) v = c[r * NF + j - NF];
    H[r * 544 + j] = __float2half_rn(v);
}
__global__ void csplit_kernel(const float* __restrict__ c, __half* __restrict__ H) {
    size_t r = blockIdx.x; int j = threadIdx.x;
    float v = (j < NF) ? c[r * NF + j] : 0.f;
    H[r * 544 + 256 + j] = __float2half_rn(v);
}
__global__ void combine_kernel() {
    int row = blockIdx.x * 256 + threadIdx.x;
    u64 b = g_tb[(size_t)row * 8], s = g_ts[(size_t)row * 8];
#pragma unroll
    for (int t = 1; t < 8; ++t) mergeBS(b, s, g_tb[(size_t)row * 8 + t], g_ts[(size_t)row * 8 + t]);
    g_key[row] = b;
    float d1 = dec_key(b), d2 = dec_key(s);
    if (d2 - d1 < 0.25f + 1e-3f * fabsf(d1)) {
        int pos = atomicAdd(&g_rcount, 1);
        if (pos < CAP) g_flag[pos] = row;
    }
}
__global__ void rgather_kernel(const float* __restrict__ x, const float* __restrict__ c) {
    int n = g_rcount; if (n > CAP) n = CAP;
    int i = blockIdx.x * 8 + (threadIdx.x >> 5);
    if (i >= n) return;
    int lane = threadIdx.x & 31;
    size_t row = (size_t)g_flag[i];
    for (int j = lane; j < NF; j += 32) {
        g_rx[(size_t)i * NF + j] = x[row * NF + j];
        g_rc[(size_t)i * NF + j] = c[row * NF + j];
    }
}
__global__ void rscatter_kernel() {
    int n = g_rcount; if (n > CAP) n = CAP;
    int i = blockIdx.x * 256 + threadIdx.x;
    if (i < n) g_key[g_flag[i]] = g_rkeys[i];
}
// counts, loss (exact-grade from mu hi+lo vs embed hi+lo), quantize hi plane
__global__ void vq_gather_kernel(const __half* __restrict__ pmh, const __half* __restrict__ pml,
                                 const __half* __restrict__ ebh, const __half* __restrict__ ebl,
                                 __half* __restrict__ H) {
    __shared__ float s_ls[8];
    const int wid = threadIdx.x >> 5, lane = threadIdx.x & 31;
    const size_t row = (size_t)blockIdx.x * 8 + wid;
    const int ind = (int)(g_key[row] & 0xFFFFFFFFull);
    if (lane == 0) atomicAdd(&g_counts[ind], 1);
    float ls = 0.f;
#pragma unroll
    for (int i = 0; i < 8; ++i) {
        int dim = i * 32 + lane;
        __half qh = ebh[(size_t)ind * 256 + dim];
        float qv = __half2float(qh) + __half2float(ebl[(size_t)ind * 256 + dim]);
        float mv = __half2float(pmh[row * 256 + dim]) + __half2float(pml[row * 256 + dim]);
        H[row * 544 + dim] = __float2half_rn(qv);   // best fp16 of exact quantize
        float d = qv - mv;
        ls += d * d;
    }
#pragma unroll
    for (int s = 16; s > 0; s >>= 1) ls += __shfl_down_sync(0xFFFFFFFF, ls, s);
    if (lane == 0) s_ls[wid] = ls;
    __syncthreads();
    if (threadIdx.x == 0) {
        double t = 0.0;
        for (int w = 0; w < 8; ++w) t += (double)s_ls[w];
        atomicAdd(&g_loss, t);
    }
}
__global__ void finalize_kernel(float* __restrict__ out) {
    __shared__ double sh[256];
    int t = threadIdx.x;
    double e = 0.0;
    for (int k = t; k < NKC; k += 256) {
        double p = (double)g_counts[k] / (double)NB;
        e += p * log(p + 1e-10);
    }
    sh[t] = e;
    __syncthreads();
    for (int s = 128; s > 0; s >>= 1) { if (t < s) sh[t] += sh[t + s]; __syncthreads(); }
    if (t == 0) {
        out[(size_t)NB * NF]     = (float)(g_loss / ((double)NB * (double)NL));
        out[(size_t)NB * NF + 1] = (float)exp(-sh[0]);
    }
}

// ======================= launch ===========================================
extern "C" void kernel_launch(void* const* d_in, const int* in_sizes, int n_in,
                              void* d_out, int out_size)
{
    const float* x     = (const float*)d_in[0];
    const float* c     = (const float*)d_in[1];
    const float* W1    = (const float*)d_in[2];
    const float* b1    = (const float*)d_in[3];
    const float* W2    = (const float*)d_in[4];
    const float* b2    = (const float*)d_in[5];
    const float* W3    = (const float*)d_in[6];
    const float* b3    = (const float*)d_in[7];
    const float* Wmu   = (const float*)d_in[8];
    const float* bmu   = (const float*)d_in[9];
    const float* W4    = (const float*)d_in[10];
    const float* b4    = (const float*)d_in[11];
    const float* W5    = (const float*)d_in[12];
    const float* b5    = (const float*)d_in[13];
    const float* W6    = (const float*)d_in[14];
    const float* b6    = (const float*)d_in[15];
    const float* Wo    = (const float*)d_in[16];
    const float* bo    = (const float*)d_in[17];
    const float* embed = (const float*)d_in[18];
    float* out = (float*)d_out;

    float *en, *rx, *rc, *rh1, *rh2, *rmu;
    u64 *keys, *tb, *ts, *rkeys;
    int* rcnt;
    __half *pxh, *pah, *pbh, *pch, *pmh, *pml;
    __half *w1h, *w1l, *w2h, *w2l, *w3h, *w3l, *wmh, *wml;
    __half *w4h, *w4l, *w5h, *w5l, *w6h, *w6l, *woh, *wol, *ebh, *ebl;
    cudaGetSymbolAddress((void**)&en,   g_enorm);
    cudaGetSymbolAddress((void**)&keys, g_key);
    cudaGetSymbolAddress((void**)&tb,   g_tb);
    cudaGetSymbolAddress((void**)&ts,   g_ts);
    cudaGetSymbolAddress((void**)&rkeys, g_rkeys);
    cudaGetSymbolAddress((void**)&rcnt, g_rcount);
    cudaGetSymbolAddress((void**)&rx,   g_rx);
    cudaGetSymbolAddress((void**)&rc,   g_rc);
    cudaGetSymbolAddress((void**)&rh1,  g_rh1);
    cudaGetSymbolAddress((void**)&rh2,  g_rh2);
    cudaGetSymbolAddress((void**)&rmu,  g_rmu);
    cudaGetSymbolAddress((void**)&pxh,  g_PXh);
    cudaGetSymbolAddress((void**)&pah,  g_PAh);
    cudaGetSymbolAddress((void**)&pbh,  g_PBh);
    cudaGetSymbolAddress((void**)&pch,  g_PCh);
    cudaGetSymbolAddress((void**)&pmh,  g_PMh);
    cudaGetSymbolAddress((void**)&pml,  g_PMl);
    cudaGetSymbolAddress((void**)&w1h,  g_w1h);  cudaGetSymbolAddress((void**)&w1l, g_w1l);
    cudaGetSymbolAddress((void**)&w2h,  g_w2h);  cudaGetSymbolAddress((void**)&w2l, g_w2l);
    cudaGetSymbolAddress((void**)&w3h,  g_w3h);  cudaGetSymbolAddress((void**)&w3l, g_w3l);
    cudaGetSymbolAddress((void**)&wmh,  g_wmh);  cudaGetSymbolAddress((void**)&wml, g_wml);
    cudaGetSymbolAddress((void**)&w4h,  g_w4h);  cudaGetSymbolAddress((void**)&w4l, g_w4l);
    cudaGetSymbolAddress((void**)&w5h,  g_w5h);  cudaGetSymbolAddress((void**)&w5l, g_w5l);
    cudaGetSymbolAddress((void**)&w6h,  g_w6h);  cudaGetSymbolAddress((void**)&w6l, g_w6l);
    cudaGetSymbolAddress((void**)&woh,  g_woh);  cudaGetSymbolAddress((void**)&wol, g_wol);
    cudaGetSymbolAddress((void**)&ebh,  g_ebh);  cudaGetSymbolAddress((void**)&ebl, g_ebl);

    cudaFuncSetAttribute(gemm2<0>, cudaFuncAttributeMaxDynamicSharedMemorySize, SMEM_BYTES);
    cudaFuncSetAttribute(gemm2<1>, cudaFuncAttributeMaxDynamicSharedMemorySize, SMEM_BYTES);
    cudaFuncSetAttribute(gemm2<2>, cudaFuncAttributeMaxDynamicSharedMemorySize, SMEM_BYTES);
    cudaFuncSetAttribute((const void*)fgemm<1, 2>, cudaFuncAttributeMaxDynamicSharedMemorySize, SMEM_F);
    cudaFuncSetAttribute((const void*)fgemm<2, 1>, cudaFuncAttributeMaxDynamicSharedMemorySize, SMEM_F);
    cudaFuncSetAttribute((const void*)fgemm<4, 2>, cudaFuncAttributeMaxDynamicSharedMemorySize, SMEM_F);
    cudaFuncSetAttribute((const void*)fgemm<5, 2>, cudaFuncAttributeMaxDynamicSharedMemorySize, SMEM_F);

    const int MT = NB / 128;   // 1024
    const int RT = CAP / 128;  // 512
    init_kernel<<<256, 256>>>();
    enorm_kernel<<<4, 256>>>(embed);
    wsplit_kernel<<<dim3(512, 3), 256>>>(W1, 534, 512, 544, w1h, w1l);
    wsplit_kernel<<<dim3(512, 2), 256>>>(W2, 512, 512, 512, w2h, w2l);
    wsplit_kernel<<<dim3(512, 2), 256>>>(W3, 512, 512, 512, w3h, w3l);
    wsplit_kernel<<<dim3(256, 2), 256>>>(Wmu, 512, 256, 512, wmh, wml);
    wsplit_kernel<<<dim3(512, 3), 256>>>(W4, 523, 512, 544, w4h, w4l);
    wsplit_kernel<<<dim3(512, 2), 256>>>(W5, 512, 512, 512, w5h, w5l);
    wsplit_kernel<<<dim3(512, 2), 256>>>(W6, 512, 512, 512, w6h, w6l);
    wsplit_kernel<<<dim3(384, 2), 256>>>(Wo, 512, 267, 512, woh, wol);
    wsplit_kernel<<<dim3(1024, 1), 256>>>(embed, 256, 1024, 256, ebh, ebl);
    xcsplit_kernel<<<NB, 544>>>(x, c, pxh);
    csplit_kernel<<<NB, 288>>>(c, pah);

    // encoder: 2-term (fp16-hi activations, hi+lo weights)
    fgemm<5, 2><<<dim3(MT, 4), 256, SMEM_F>>>(pxh, pxh, 544, w1h, w1l, 544, b1, 544, 0, pbh, 0, 512, 512, 0, 0);
    fgemm<5, 2><<<dim3(MT, 4), 256, SMEM_F>>>(pbh, pbh, 512, w2h, w2l, 512, b2, 512, 0, pch, 0, 512, 512, 0, 0);
    fgemm<5, 2><<<dim3(MT, 4), 256, SMEM_F>>>(pch, pch, 512, w3h, w3l, 512, b3, 512, 0, pbh, 0, 512, 512, 0, 0);
    fgemm<4, 2><<<dim3(MT, 2), 256, SMEM_F>>>(pbh, pbh, 512, wmh, wml, 512, bmu, 512, 0, pmh, pml, 256, 256, 0, 0);
    // VQ 1-term (margin + exact repair protect the argmin)
    fgemm<2, 1><<<dim3(MT, 8), 256, SMEM_F>>>(pmh, pmh, 256, ebh, ebh, 256, en, 256, 0, 0, 0, 0, NKC, tb, ts);
    combine_kernel<<<512, 256>>>();
    // exact fp32 repair of near-tie rows
    rgather_kernel<<<CAP / 8, 256>>>(x, c);
    gemm2<0><<<dim3(RT, 2), 256, SMEM_BYTES>>>(rx, NF, rc, 2 * NF, W1, b1, rh1, NH, 0, rcnt);
    gemm2<0><<<dim3(RT, 2), 256, SMEM_BYTES>>>(rh1, NH, 0, NH, W2, b2, rh2, NH, 0, rcnt);
    gemm2<0><<<dim3(RT, 2), 256, SMEM_BYTES>>>(rh2, NH, 0, NH, W3, b3, rh1, NH, 0, rcnt);
    gemm2<1><<<dim3(RT, 1), 256, SMEM_BYTES>>>(rh1, NH, 0, NH, Wmu, bmu, rmu, NL, 0, rcnt);
    gemm2<2><<<dim3(RT, 4), 256, SMEM_BYTES>>>(rmu, NL, 0, NL, embed, en, 0, NKC, rkeys, rcnt);
    rscatter_kernel<<<CAP / 256, 256>>>();
    // gather + decoder: 2-term (fp16-hi activations, hi+lo weights)
    vq_gather_kernel<<<NB / 8, 256>>>(pmh, pml, ebh, ebl, pah);
    fgemm<5, 2><<<dim3(MT, 4), 256, SMEM_F>>>(pah, pah, 544, w4h, w4l, 544, b4, 544, 0, pch, 0, 512, 512, 0, 0);
    fgemm<5, 2><<<dim3(MT, 4), 256, SMEM_F>>>(pch, pch, 512, w5h, w5l, 512, b5, 512, 0, pbh, 0, 512, 512, 0, 0);
    fgemm<5, 2><<<dim3(MT, 4), 256, SMEM_F>>>(pbh, pbh, 512, w6h, w6l, 512, b6, 512, 0, pch, 0, 512, 512, 0, 0);
    fgemm<1, 2><<<dim3(MT, 3), 256, SMEM_F>>>(pch, pch, 512, woh, wol, 512, bo, 512, out, 0, 0, NF, NF, 0, 0);
    finalize_kernel<<<1, 256>>>(out);
}

// round 16
// speedup vs baseline: 1.4661x; 1.1305x over previous
#include <cuda_runtime.h>
#include <cuda_fp16.h>
#include <math.h>
#include <stdint.h>

#define NB 131072
#define NH 512
#define NL 256
#define NKC 1024
#define NF 267
#define CAP 65536
#define KTILE 32
#define TILE_F (KTILE * 256)
#define SMEM_BYTES (2 * 2 * TILE_F * 4)

typedef unsigned long long u64;
typedef unsigned int u32;

// ---------------- scratch ----------------
__device__ float  g_enorm[NKC];
__device__ u64    g_key[NB];
__device__ u64    g_tb[(size_t)NB * 8];
__device__ u64    g_ts[(size_t)NB * 8];
__device__ int    g_counts[NKC];
__device__ double g_loss;
__device__ int    g_rcount;
__device__ int    g_flag[CAP];
__device__ u64    g_rkeys[CAP];
// repair fp32 buffers
__device__ float  g_rx[(size_t)CAP * NF];
__device__ float  g_rc[(size_t)CAP * NF];
__device__ float  g_rh1[(size_t)CAP * NH];
__device__ float  g_rh2[(size_t)CAP * NH];
__device__ float  g_rmu[(size_t)CAP * NL];
// fp16 activation planes (hi-only; mu keeps lo for loss)
__device__ __half g_PXh[(size_t)NB * 576];
__device__ __half g_PAh[(size_t)NB * 576];
__device__ __half g_PBh[(size_t)NB * 512];
__device__ __half g_PCh[(size_t)NB * 512];
__device__ __half g_PMh[(size_t)NB * 256], g_PMl[(size_t)NB * 256];
// fp16 weight planes [Npad][Kpad]
__device__ __half g_w1h[512 * 576], g_w1l[512 * 576];
__device__ __half g_w2h[512 * 512], g_w2l[512 * 512];
__device__ __half g_w3h[512 * 512], g_w3l[512 * 512];
__device__ __half g_wmh[256 * 512], g_wml[256 * 512];
__device__ __half g_w4h[512 * 576], g_w4l[512 * 576];
__device__ __half g_w5h[512 * 512], g_w5l[512 * 512];
__device__ __half g_w6h[512 * 512], g_w6l[512 * 512];
__device__ __half g_woh[384 * 512], g_wol[384 * 512];
__device__ __half g_ebh[1024 * 256], g_ebl[1024 * 256];

#define FFMA2(d, a, b) asm("fma.rn.f32x2 %0, %1, %2, %0;" : "+l"(d) : "l"(a), "l"(b))
__device__ __forceinline__ u64 dupf(float v) {
    u64 r; asm("mov.b64 %0, {%1, %1};" : "=l"(r) : "f"(v)); return r;
}
__device__ __forceinline__ float lof(u64 v) { return __uint_as_float((unsigned)v); }
__device__ __forceinline__ float hif(u64 v) { return __uint_as_float((unsigned)(v >> 32)); }
__device__ __forceinline__ u32 smem_u32(const void* p) {
    u32 a;
    asm("{ .reg .u64 t; cvta.to.shared.u64 t, %1; cvt.u32.u64 %0, t; }" : "=r"(a) : "l"(p));
    return a;
}
__device__ __forceinline__ void ldsm4(u32* r, u32 addr) {
    asm volatile("ldmatrix.sync.aligned.m8n8.x4.shared.b16 {%0,%1,%2,%3}, [%4];"
        : "=r"(r[0]), "=r"(r[1]), "=r"(r[2]), "=r"(r[3]) : "r"(addr));
}
__device__ __forceinline__ void mmah(float* c, const u32* a, u32 b0, u32 b1) {
    asm volatile("mma.sync.aligned.m16n8k16.row.col.f32.f16.f16.f32 "
        "{%0,%1,%2,%3}, {%4,%5,%6,%7}, {%8,%9}, {%0,%1,%2,%3};"
        : "+f"(c[0]), "+f"(c[1]), "+f"(c[2]), "+f"(c[3])
        : "r"(a[0]), "r"(a[1]), "r"(a[2]), "r"(a[3]), "r"(b0), "r"(b1));
}
__device__ __forceinline__ u64 enc_key(float d, int col) {
    unsigned u = __float_as_uint(d);
    u = (u & 0x80000000u) ? ~u : (u | 0x80000000u);
    return ((u64)u << 32) | (unsigned)col;
}
__device__ __forceinline__ float dec_key(u64 k) {
    unsigned u = (unsigned)(k >> 32);
    u = (u & 0x80000000u) ? (u & 0x7FFFFFFFu) : ~u;
    return __uint_as_float(u);
}
__device__ __forceinline__ void mergeBS(u64& b, u64& s, u64 b2, u64 s2) {
    if (b2 < b) { u64 t = b < s2 ? b : s2; b = b2; s = t; }
    else        { if (b2 < s) s = b2; }
}

// ======================= fp32 FFMA2 GEMM (repair path) =====================
template <int MODE>   // 0 relu, 1 linear, 2 VQ argmin
__global__ void __launch_bounds__(256, 1) gemm2(
    const float* __restrict__ A0, int K0,
    const float* __restrict__ A1, int Ktot,
    const float* __restrict__ W, const float* __restrict__ bias,
    float* __restrict__ C, int N, u64* __restrict__ keys,
    const int* __restrict__ cnt)
{
    extern __shared__ float dyn[];
    float* As = dyn;
    float* Ws = dyn + 2 * TILE_F;

    const int tid = threadIdx.x;
    const int tx = tid & 15, ty = tid >> 4;
    const int m0 = blockIdx.x * 128, n0 = blockIdx.y * 256;
    if (cnt) { int n = *cnt; if (n > CAP) n = CAP; if (m0 >= n) return; }
    const int K1 = Ktot - K0;
    const int am = tid >> 1;
    const int ak = (tid & 1) * 16;
    const int nT = (Ktot + KTILE - 1) / KTILE;

    u64 acc[8][8];
#pragma unroll
    for (int i = 0; i < 8; ++i)
#pragma unroll
        for (int j = 0; j < 8; ++j) acc[i][j] = 0ull;

    float  aReg[16];
    float4 bReg[8];

#define LOADA(kt) do {                                                        \
    _Pragma("unroll")                                                         \
    for (int q = 0; q < 16; ++q) {                                            \
        int k = (kt) * KTILE + ak + q;                                        \
        float v = 0.f;                                                        \
        if (k < K0)        v = A0[(size_t)(m0 + am) * K0 + k];                \
        else if (k < Ktot) v = A1[(size_t)(m0 + am) * K1 + (k - K0)];         \
        aReg[q] = v;                                                          \
    } } while (0)

#define LOADB(kt) do {                                                        \
    _Pragma("unroll")                                                         \
    for (int i = 0; i < 8; ++i) {                                             \
        int idx = tid + i * 256;                                              \
        int k = idx >> 6, n4 = (idx & 63) * 4;                                \
        int kg = (kt) * KTILE + k;                                            \
        int ng = n0 + n4;                                                     \
        float4 v = make_float4(0.f, 0.f, 0.f, 0.f);                           \
        if (kg < Ktot && ng < N) v = *(const float4*)&W[(size_t)kg * N + ng]; \
        bReg[i] = v;                                                          \
    } } while (0)

#define STST(p) do {                                                          \
    float* ab = As + (p) * TILE_F;                                            \
    _Pragma("unroll")                                                         \
    for (int q = 0; q < 16; ++q)                                              \
        *(u64*)(ab + (ak + q) * 256 + 2 * am) = dupf(aReg[q]);                \
    float* wb = Ws + (p) * TILE_F;                                            \
    _Pragma("unroll")                                                         \
    for (int i = 0; i < 8; ++i) {                                             \
        int idx = tid + i * 256;                                              \
        *(float4*)(wb + (idx >> 6) * 256 + (idx & 63) * 4) = bReg[i];         \
    } } while (0)

    LOADA(0); LOADB(0);
    STST(0);
    __syncthreads();

    for (int kt = 0; kt < nT; ++kt) {
        const int p = kt & 1;
        if (kt + 1 < nT) { LOADA(kt + 1); LOADB(kt + 1); }
        const float* ab = As + p * TILE_F + ty * 16;
        const float* wb = Ws + p * TILE_F + tx * 4;
#pragma unroll 4
        for (int k = 0; k < KTILE; ++k) {
            u64 a[8], b[8];
            const ulonglong2* ap = (const ulonglong2*)(ab + k * 256);
#pragma unroll
            for (int q = 0; q < 4; ++q) { ulonglong2 t = ap[q]; a[2*q] = t.x; a[2*q+1] = t.y; }
#pragma unroll
            for (int q = 0; q < 4; ++q) {
                ulonglong2 t = *(const ulonglong2*)(wb + k * 256 + q * 64);
                b[2*q] = t.x; b[2*q+1] = t.y;
            }
#pragma unroll
            for (int i = 0; i < 8; ++i)
#pragma unroll
                for (int j = 0; j < 8; ++j) FFMA2(acc[i][j], a[i], b[j]);
        }
        if (kt + 1 < nT) STST((kt + 1) & 1);
        __syncthreads();
    }

    if (MODE == 2) {
        u64* red = (u64*)dyn;
#pragma unroll
        for (int i = 0; i < 8; ++i) {
            u64 best = ~0ull;
#pragma unroll
            for (int j = 0; j < 8; ++j) {
                int c0 = n0 + (j >> 1) * 64 + tx * 4 + (j & 1) * 2;
                u64 k0 = enc_key(bias[c0]     - 2.f * lof(acc[i][j]), c0);
                u64 k1 = enc_key(bias[c0 + 1] - 2.f * hif(acc[i][j]), c0 + 1);
                if (k0 < best) best = k0;
                if (k1 < best) best = k1;
            }
            red[(ty * 8 + i) * 17 + tx] = best;
        }
        __syncthreads();
        if (tid < 128) {
            u64 b = red[tid * 17];
#pragma unroll
            for (int x = 1; x < 16; ++x) { u64 v = red[tid * 17 + x]; if (v < b) b = v; }
            atomicMin(&keys[m0 + tid], b);
        }
        return;
    }

#pragma unroll
    for (int i = 0; i < 8; ++i) {
        size_t row = (size_t)(m0 + ty * 8 + i);
#pragma unroll
        for (int j = 0; j < 8; ++j) {
            int c0 = n0 + (j >> 1) * 64 + tx * 4 + (j & 1) * 2;
            if (c0 < N) {
                float v = lof(acc[i][j]) + bias[c0];
                if (MODE == 0) v = fmaxf(v, 0.f);
                C[row * N + c0] = v;
            }
            if (c0 + 1 < N) {
                float v = hif(acc[i][j]) + bias[c0 + 1];
                if (MODE == 0) v = fmaxf(v, 0.f);
                C[row * N + c0 + 1] = v;
            }
        }
    }
#undef LOADA
#undef LOADB
#undef STST
}

// ======= fp16-plane mma.sync GEMM, cp.async 3-stage, KTILE=64 ==============
// TERMS: 2 = Ah*Bh + Ah*Bl | 1 = Ah*Bh
// MODE 1: linear -> fp32, N guard | 2: VQ best/2nd
//      4: linear -> hi+lo planes | 5: relu -> hi plane only
// Stage: A 128 rows x 128B (hi, 8x16B chunks) + B 128 rows x 256B (hi|lo)
#define FSTG 49152
#define SMEM_F (3 * FSTG)

template <int MODE, int TERMS>
__global__ void __launch_bounds__(256, 1) fgemm(
    const __half* __restrict__ Ah, int lda,
    const __half* __restrict__ Bh, const __half* __restrict__ Bl, int ldb,
    const float* __restrict__ bias, int Ktot,
    float* __restrict__ outF, __half* __restrict__ outH, __half* __restrict__ outL,
    int ldo, int N, u64* __restrict__ tb, u64* __restrict__ ts)
{
    extern __shared__ char smraw[];
    const u32 smem = smem_u32(smraw);

    const int tid = threadIdx.x;
    const int lane = tid & 31, wid = tid >> 5;
    const int wm = (wid >> 1) * 32, wn = (wid & 1) * 64;
    const int g = lane >> 2, tg = lane & 3;
    const int m0 = blockIdx.x * 128, n0 = blockIdx.y * 128;
    const int nT = Ktot >> 6;

    const int lx = lane & 7;
    const int mA = wm + lx + ((lane & 8) ? 8 : 0);
    const int cA = (lane >> 4) & 1;
    const int nB = wn + lx + ((lane & 16) ? 8 : 0);
    const int cB = (lane >> 3) & 1;

    float acc[2][8][4];
#pragma unroll
    for (int mt = 0; mt < 2; ++mt)
#pragma unroll
        for (int j = 0; j < 8; ++j)
#pragma unroll
            for (int q = 0; q < 4; ++q) acc[mt][j][q] = 0.f;

#define ISSUE(kt) do {                                                         \
    u32 st = smem + ((kt) % 3) * FSTG;                                         \
    _Pragma("unroll")                                                          \
    for (int i = 0; i < 4; ++i) {      /* A: 128 rows x 8 hi chunks */         \
        int idx = tid + i * 256; int m = idx >> 3, cc = idx & 7;               \
        const __half* src = Ah + (size_t)(m0 + m) * lda + (kt) * 64 + cc * 8;  \
        u32 dst = st + m * 128 + ((cc ^ (m & 7)) << 4);                        \
        asm volatile("cp.async.ca.shared.global [%0], [%1], 16;"               \
                     :: "r"(dst), "l"(src));                                   \
    }                                                                          \
    {                                                                          \
        const int CH = (TERMS >= 2) ? 16 : 8;                                  \
        _Pragma("unroll")                                                      \
        for (int i = 0; i < CH / 2; ++i) {                                     \
            int idx = tid + i * 256;                                           \
            int n = idx / CH, cc = idx % CH;                                   \
            bool lo = (cc >= 8);                                               \
            const __half* src = (lo ? Bl : Bh)                                 \
                + (size_t)(n0 + n) * ldb + (kt) * 64 + (cc & 7) * 8;           \
            u32 dst = st + 16384 + n * 256 + (lo ? 128 : 0)                    \
                      + (((cc & 7) ^ (n & 7)) << 4);                           \
            asm volatile("cp.async.ca.shared.global [%0], [%1], 16;"           \
                         :: "r"(dst), "l"(src));                               \
        }                                                                      \
    }                                                                          \
    asm volatile("cp.async.commit_group;"); } while (0)

    ISSUE(0); ISSUE(1);

    for (int kt = 0; kt < nT; ++kt) {
        if (kt + 1 < nT) asm volatile("cp.async.wait_group 1;");
        else             asm volatile("cp.async.wait_group 0;");
        __syncthreads();

        const u32 Abase = smem + (kt % 3) * FSTG;
        const u32 Bbase = Abase + 16384;
#pragma unroll
        for (int s = 0; s < 4; ++s) {   // 4 k16 steps per 64-k tile
            const int chA = 2 * s + cA;
            const int chB = 2 * s + cB;
            u32 ah[2][4];
#pragma unroll
            for (int mt = 0; mt < 2; ++mt) {
                u32 rowa = Abase + (mA + mt * 16) * 128;
                ldsm4(ah[mt], rowa + ((chA ^ lx) << 4));
            }
#pragma unroll
            for (int jp = 0; jp < 4; ++jp) {
                u32 bh[4], bl[4];
                u32 rowb = Bbase + (nB + jp * 16) * 256;
                ldsm4(bh, rowb + ((chB ^ lx) << 4));
                if (TERMS >= 2) ldsm4(bl, rowb + 128 + ((chB ^ lx) << 4));
#pragma unroll
                for (int mt = 0; mt < 2; ++mt)
#pragma unroll
                    for (int jj = 0; jj < 2; ++jj) {
                        float* a = acc[mt][jp * 2 + jj];
                        mmah(a, ah[mt], bh[2*jj], bh[2*jj+1]);
                        if (TERMS >= 2) mmah(a, ah[mt], bl[2*jj], bl[2*jj+1]);
                    }
            }
        }
        if (kt + 2 < nT) ISSUE(kt + 2);
    }
#undef ISSUE

    if (MODE == 2) {
        __syncthreads();
        u64* pb = (u64*)smraw;          // [128][8]
        u64* ps = pb + 128 * 8;
        const int slot = (wid & 1) * 4 + tg;
#pragma unroll
        for (int mt = 0; mt < 2; ++mt)
#pragma unroll
            for (int dq = 0; dq < 2; ++dq) {
                int rl = wm + mt * 16 + g + dq * 8;
                u64 b = ~0ull, s = ~0ull;
#pragma unroll
                for (int j = 0; j < 8; ++j)
#pragma unroll
                    for (int c01 = 0; c01 < 2; ++c01) {
                        int col = n0 + wn + j * 8 + 2 * tg + c01;
                        u64 k = enc_key(bias[col] - 2.f * acc[mt][j][dq * 2 + c01], col);
                        if (k < b) { s = b; b = k; } else if (k < s) s = k;
                    }
                pb[rl * 8 + slot] = b;
                ps[rl * 8 + slot] = s;
            }
        __syncthreads();
        if (tid < 128) {
            u64 b = pb[tid * 8], s = ps[tid * 8];
#pragma unroll
            for (int k = 1; k < 8; ++k) mergeBS(b, s, pb[tid * 8 + k], ps[tid * 8 + k]);
            tb[(size_t)(m0 + tid) * 8 + blockIdx.y] = b;
            ts[(size_t)(m0 + tid) * 8 + blockIdx.y] = s;
        }
        return;
    }

#pragma unroll
    for (int mt = 0; mt < 2; ++mt) {
        int r0 = m0 + wm + mt * 16 + g;
#pragma unroll
        for (int j = 0; j < 8; ++j) {
            int c0 = n0 + wn + j * 8 + 2 * tg;
            if (MODE == 4 || MODE == 5) {
                float b0 = bias[c0], b1 = bias[c0 + 1];
                float v0 = acc[mt][j][0] + b0, v1 = acc[mt][j][1] + b1;
                float v2 = acc[mt][j][2] + b0, v3 = acc[mt][j][3] + b1;
                if (MODE != 4) {
                    v0 = fmaxf(v0, 0.f); v1 = fmaxf(v1, 0.f);
                    v2 = fmaxf(v2, 0.f); v3 = fmaxf(v3, 0.f);
                }
                __half h0 = __float2half_rn(v0), h1 = __float2half_rn(v1);
                __half h2 = __float2half_rn(v2), h3 = __float2half_rn(v3);
                *(__half2*)(outH + (size_t)r0 * ldo + c0) = __halves2half2(h0, h1);
                *(__half2*)(outH + (size_t)(r0 + 8) * ldo + c0) = __halves2half2(h2, h3);
                if (MODE == 4) {
                    *(__half2*)(outL + (size_t)r0 * ldo + c0) = __halves2half2(
                        __float2half_rn(v0 - __half2float(h0)),
                        __float2half_rn(v1 - __half2float(h1)));
                    *(__half2*)(outL + (size_t)(r0 + 8) * ldo + c0) = __halves2half2(
                        __float2half_rn(v2 - __half2float(h2)),
                        __float2half_rn(v3 - __half2float(h3)));
                }
            } else {
                float b0 = (c0 < N) ? bias[c0] : 0.f;
                float b1 = (c0 + 1 < N) ? bias[c0 + 1] : 0.f;
                if (c0 < N) {
                    outF[(size_t)r0 * ldo + c0]       = acc[mt][j][0] + b0;
                    outF[(size_t)(r0 + 8) * ldo + c0] = acc[mt][j][2] + b0;
                }
                if (c0 + 1 < N) {
                    outF[(size_t)r0 * ldo + c0 + 1]       = acc[mt][j][1] + b1;
                    outF[(size_t)(r0 + 8) * ldo + c0 + 1] = acc[mt][j][3] + b1;
                }
            }
        }
    }
}

// ======================= prep / combine / repair kernels ===================
__global__ void init_kernel(const float* __restrict__ e) {
    int t = blockIdx.x * 256 + threadIdx.x;
    if (t < NKC) {
        g_counts[t] = 0;
        float s = 0.f;
        for (int l = 0; l < NL; ++l) { float v = e[(size_t)l * NKC + t]; s += v * v; }
        g_enorm[t] = s;
    }
    if (t < CAP) g_rkeys[t] = ~0ull;
    if (t == 0) { g_loss = 0.0; g_rcount = 0; }
}
__global__ void wsplit_kernel(const float* __restrict__ W, int K, int N, int Kpad,
                              __half* __restrict__ H, __half* __restrict__ L) {
    int n = blockIdx.x;
    int k = blockIdx.y * 256 + threadIdx.x;
    if (k >= Kpad) return;
    float v = (k < K && n < N) ? W[(size_t)k * N + n] : 0.f;
    __half h = __float2half_rn(v);
    size_t o = (size_t)n * Kpad + k;
    H[o] = h;
    L[o] = __float2half_rn(v - __half2float(h));
}
__global__ void xcsplit_kernel(const float* __restrict__ x, const float* __restrict__ c,
                               __half* __restrict__ H) {
    size_t r = blockIdx.x; int j = threadIdx.x;   // 0..575
    float v = 0.f;
    if (j < NF) v = x[r * NF + j];
    else if (j < 2 * NF) v = c[r * NF + j - NF];
    H[r * 576 + j] = __float2half_rn(v);
}
__global__ void csplit_kernel(const float* __restrict__ c, __half* __restrict__ H) {
    size_t r = blockIdx.x; int j = threadIdx.x;   // 0..319
    float v = (j < NF) ? c[r * NF + j] : 0.f;
    H[r * 576 + 256 + j] = __float2half_rn(v);
}
// merge best/second, flag + gather near-tie rows in one pass
__global__ void combine_kernel(const float* __restrict__ x, const float* __restrict__ c) {
    int row = blockIdx.x * 256 + threadIdx.x;
    u64 b = g_tb[(size_t)row * 8], s = g_ts[(size_t)row * 8];
#pragma unroll
    for (int t = 1; t < 8; ++t) mergeBS(b, s, g_tb[(size_t)row * 8 + t], g_ts[(size_t)row * 8 + t]);
    g_key[row] = b;
    float d1 = dec_key(b), d2 = dec_key(s);
    if (d2 - d1 < 0.25f + 1e-3f * fabsf(d1)) {
        int pos = atomicAdd(&g_rcount, 1);
        if (pos < CAP) {
            g_flag[pos] = row;
            const float* xs = x + (size_t)row * NF;
            const float* cs = c + (size_t)row * NF;
            float* xd = g_rx + (size_t)pos * NF;
            float* cd = g_rc + (size_t)pos * NF;
            for (int j = 0; j < NF; ++j) { xd[j] = xs[j]; cd[j] = cs[j]; }
        }
    }
}
__global__ void rscatter_kernel() {
    int n = g_rcount; if (n > CAP) n = CAP;
    int i = blockIdx.x * 256 + threadIdx.x;
    if (i < n) g_key[g_flag[i]] = g_rkeys[i];
}
// counts, loss (mu hi+lo vs embed hi+lo), quantize hi plane
__global__ void vq_gather_kernel(const __half* __restrict__ pmh, const __half* __restrict__ pml,
                                 const __half* __restrict__ ebh, const __half* __restrict__ ebl,
                                 __half* __restrict__ H) {
    __shared__ float s_ls[8];
    const int wid = threadIdx.x >> 5, lane = threadIdx.x & 31;
    const size_t row = (size_t)blockIdx.x * 8 + wid;
    const int ind = (int)(g_key[row] & 0xFFFFFFFFull);
    if (lane == 0) atomicAdd(&g_counts[ind], 1);
    float ls = 0.f;
#pragma unroll
    for (int i = 0; i < 8; ++i) {
        int dim = i * 32 + lane;
        __half qh = ebh[(size_t)ind * 256 + dim];
        float qv = __half2float(qh) + __half2float(ebl[(size_t)ind * 256 + dim]);
        float mv = __half2float(pmh[row * 256 + dim]) + __half2float(pml[row * 256 + dim]);
        H[row * 576 + dim] = __float2half_rn(qv);
        float d = qv - mv;
        ls += d * d;
    }
#pragma unroll
    for (int s = 16; s > 0; s >>= 1) ls += __shfl_down_sync(0xFFFFFFFF, ls, s);
    if (lane == 0) s_ls[wid] = ls;
    __syncthreads();
    if (threadIdx.x == 0) {
        double t = 0.0;
        for (int w = 0; w < 8; ++w) t += (double)s_ls[w];
        atomicAdd(&g_loss, t);
    }
}
__global__ void finalize_kernel(float* __restrict__ out) {
    __shared__ double sh[256];
    int t = threadIdx.x;
    double e = 0.0;
    for (int k = t; k < NKC; k += 256) {
        double p = (double)g_counts[k] / (double)NB;
        e += p * log(p + 1e-10);
    }
    sh[t] = e;
    __syncthreads();
    for (int s = 128; s > 0; s >>= 1) { if (t < s) sh[t] += sh[t + s]; __syncthreads(); }
    if (t == 0) {
        out[(size_t)NB * NF]     = (float)(g_loss / ((double)NB * (double)NL));
        out[(size_t)NB * NF + 1] = (float)exp(-sh[0]);
    }
}

// ======================= launch ===========================================
extern "C" void kernel_launch(void* const* d_in, const int* in_sizes, int n_in,
                              void* d_out, int out_size)
{
    const float* x     = (const float*)d_in[0];
    const float* c     = (const float*)d_in[1];
    const float* W1    = (const float*)d_in[2];
    const float* b1    = (const float*)d_in[3];
    const float* W2    = (const float*)d_in[4];
    const float* b2    = (const float*)d_in[5];
    const float* W3    = (const float*)d_in[6];
    const float* b3    = (const float*)d_in[7];
    const float* Wmu   = (const float*)d_in[8];
    const float* bmu   = (const float*)d_in[9];
    const float* W4    = (const float*)d_in[10];
    const float* b4    = (const float*)d_in[11];
    const float* W5    = (const float*)d_in[12];
    const float* b5    = (const float*)d_in[13];
    const float* W6    = (const float*)d_in[14];
    const float* b6    = (const float*)d_in[15];
    const float* Wo    = (const float*)d_in[16];
    const float* bo    = (const float*)d_in[17];
    const float* embed = (const float*)d_in[18];
    float* out = (float*)d_out;

    float *en, *rx, *rc, *rh1, *rh2, *rmu;
    u64 *keys, *tb, *ts, *rkeys;
    int* rcnt;
    __half *pxh, *pah, *pbh, *pch, *pmh, *pml;
    __half *w1h, *w1l, *w2h, *w2l, *w3h, *w3l, *wmh, *wml;
    __half *w4h, *w4l, *w5h, *w5l, *w6h, *w6l, *woh, *wol, *ebh, *ebl;
    cudaGetSymbolAddress((void**)&en,   g_enorm);
    cudaGetSymbolAddress((void**)&keys, g_key);
    cudaGetSymbolAddress((void**)&tb,   g_tb);
    cudaGetSymbolAddress((void**)&ts,   g_ts);
    cudaGetSymbolAddress((void**)&rkeys, g_rkeys);
    cudaGetSymbolAddress((void**)&rcnt, g_rcount);
    cudaGetSymbolAddress((void**)&rx,   g_rx);
    cudaGetSymbolAddress((void**)&rc,   g_rc);
    cudaGetSymbolAddress((void**)&rh1,  g_rh1);
    cudaGetSymbolAddress((void**)&rh2,  g_rh2);
    cudaGetSymbolAddress((void**)&rmu,  g_rmu);
    cudaGetSymbolAddress((void**)&pxh,  g_PXh);
    cudaGetSymbolAddress((void**)&pah,  g_PAh);
    cudaGetSymbolAddress((void**)&pbh,  g_PBh);
    cudaGetSymbolAddress((void**)&pch,  g_PCh);
    cudaGetSymbolAddress((void**)&pmh,  g_PMh);
    cudaGetSymbolAddress((void**)&pml,  g_PMl);
    cudaGetSymbolAddress((void**)&w1h,  g_w1h);  cudaGetSymbolAddress((void**)&w1l, g_w1l);
    cudaGetSymbolAddress((void**)&w2h,  g_w2h);  cudaGetSymbolAddress((void**)&w2l, g_w2l);
    cudaGetSymbolAddress((void**)&w3h,  g_w3h);  cudaGetSymbolAddress((void**)&w3l, g_w3l);
    cudaGetSymbolAddress((void**)&wmh,  g_wmh);  cudaGetSymbolAddress((void**)&wml, g_wml);
    cudaGetSymbolAddress((void**)&w4h,  g_w4h);  cudaGetSymbolAddress((void**)&w4l, g_w4l);
    cudaGetSymbolAddress((void**)&w5h,  g_w5h);  cudaGetSymbolAddress((void**)&w5l, g_w5l);
    cudaGetSymbolAddress((void**)&w6h,  g_w6h);  cudaGetSymbolAddress((void**)&w6l, g_w6l);
    cudaGetSymbolAddress((void**)&woh,  g_woh);  cudaGetSymbolAddress((void**)&wol, g_wol);
    cudaGetSymbolAddress((void**)&ebh,  g_ebh);  cudaGetSymbolAddress((void**)&ebl, g_ebl);

    cudaFuncSetAttribute(gemm2<0>, cudaFuncAttributeMaxDynamicSharedMemorySize, SMEM_BYTES);
    cudaFuncSetAttribute(gemm2<1>, cudaFuncAttributeMaxDynamicSharedMemorySize, SMEM_BYTES);
    cudaFuncSetAttribute(gemm2<2>, cudaFuncAttributeMaxDynamicSharedMemorySize, SMEM_BYTES);
    cudaFuncSetAttribute((const void*)fgemm<1, 2>, cudaFuncAttributeMaxDynamicSharedMemorySize, SMEM_F);
    cudaFuncSetAttribute((const void*)fgemm<2, 1>, cudaFuncAttributeMaxDynamicSharedMemorySize, SMEM_F);
    cudaFuncSetAttribute((const void*)fgemm<4, 2>, cudaFuncAttributeMaxDynamicSharedMemorySize, SMEM_F);
    cudaFuncSetAttribute((const void*)fgemm<5, 2>, cudaFuncAttributeMaxDynamicSharedMemorySize, SMEM_F);

    const int MT = NB / 128;   // 1024
    const int RT = CAP / 128;  // 512
    init_kernel<<<256, 256>>>(embed);
    wsplit_kernel<<<dim3(512, 3), 256>>>(W1, 534, 512, 576, w1h, w1l);
    wsplit_kernel<<<dim3(512, 2), 256>>>(W2, 512, 512, 512, w2h, w2l);
    wsplit_kernel<<<dim3(512, 2), 256>>>(W3, 512, 512, 512, w3h, w3l);
    wsplit_kernel<<<dim3(256, 2), 256>>>(Wmu, 512, 256, 512, wmh, wml);
    wsplit_kernel<<<dim3(512, 3), 256>>>(W4, 523, 512, 576, w4h, w4l);
    wsplit_kernel<<<dim3(512, 2), 256>>>(W5, 512, 512, 512, w5h, w5l);
    wsplit_kernel<<<dim3(512, 2), 256>>>(W6, 512, 512, 512, w6h, w6l);
    wsplit_kernel<<<dim3(384, 2), 256>>>(Wo, 512, 267, 512, woh, wol);
    wsplit_kernel<<<dim3(1024, 1), 256>>>(embed, 256, 1024, 256, ebh, ebl);
    xcsplit_kernel<<<NB, 576>>>(x, c, pxh);
    csplit_kernel<<<NB, 320>>>(c, pah);

    // encoder: 2-term fp16
    fgemm<5, 2><<<dim3(MT, 4), 256, SMEM_F>>>(pxh, 576, w1h, w1l, 576, b1, 576, 0, pbh, 0, 512, 512, 0, 0);
    fgemm<5, 2><<<dim3(MT, 4), 256, SMEM_F>>>(pbh, 512, w2h, w2l, 512, b2, 512, 0, pch, 0, 512, 512, 0, 0);
    fgemm<5, 2><<<dim3(MT, 4), 256, SMEM_F>>>(pch, 512, w3h, w3l, 512, b3, 512, 0, pbh, 0, 512, 512, 0, 0);
    fgemm<4, 2><<<dim3(MT, 2), 256, SMEM_F>>>(pbh, 512, wmh, wml, 512, bmu, 512, 0, pmh, pml, 256, 256, 0, 0);
    // VQ 1-term
    fgemm<2, 1><<<dim3(MT, 8), 256, SMEM_F>>>(pmh, 256, ebh, ebh, 256, en, 256, 0, 0, 0, 0, NKC, tb, ts);
    combine_kernel<<<512, 256>>>(x, c);
    // exact fp32 repair of near-tie rows
    gemm2<0><<<dim3(RT, 2), 256, SMEM_BYTES>>>(rx, NF, rc, 2 * NF, W1, b1, rh1, NH, 0, rcnt);
    gemm2<0><<<dim3(RT, 2), 256, SMEM_BYTES>>>(rh1, NH, 0, NH, W2, b2, rh2, NH, 0, rcnt);
    gemm2<0><<<dim3(RT, 2), 256, SMEM_BYTES>>>(rh2, NH, 0, NH, W3, b3, rh1, NH, 0, rcnt);
    gemm2<1><<<dim3(RT, 1), 256, SMEM_BYTES>>>(rh1, NH, 0, NH, Wmu, bmu, rmu, NL, 0, rcnt);
    gemm2<2><<<dim3(RT, 4), 256, SMEM_BYTES>>>(rmu, NL, 0, NL, embed, en, 0, NKC, rkeys, rcnt);
    rscatter_kernel<<<CAP / 256, 256>>>();
    // gather + decoder: 2-term fp16
    vq_gather_kernel<<<NB / 8, 256>>>(pmh, pml, ebh, ebl, pah);
    fgemm<5, 2><<<dim3(MT, 4), 256, SMEM_F>>>(pah, 576, w4h, w4l, 576, b4, 576, 0, pch, 0, 512, 512, 0, 0);
    fgemm<5, 2><<<dim3(MT, 4), 256, SMEM_F>>>(pch, 512, w5h, w5l, 512, b5, 512, 0, pbh, 0, 512, 512, 0, 0);
    fgemm<5, 2><<<dim3(MT, 4), 256, SMEM_F>>>(pbh, 512, w6h, w6l, 512, b6, 512, 0, pch, 0, 512, 512, 0, 0);
    fgemm<1, 2><<<dim3(MT, 3), 256, SMEM_F>>>(pch, 512, woh, wol, 512, bo, 512, out, 0, 0, NF, NF, 0, 0);
    finalize_kernel<<<1, 256>>>(out);
}